// round 2
// baseline (speedup 1.0000x reference)
#include <cuda_runtime.h>
#include <cstdint>

// ---------------------------------------------------------------------------
// BasicBlock_Sparse: two sparse-coding layers + shortcut, fp32.
//   layer0: conv3x3 s2 (64->512), topk16, adjoint-recon aux, 1x1 proj (512->128), BN
//   layer1: conv3x3 s1 (128->512), topk16, adjoint-recon aux, 1x1 proj, BN
//   shortcut: 1x1 s2 (64->128), BN;  out = relu(l1 + sc)
// Output: [64,128,28,28] flat, then aux0, aux1.
//
// CRITICAL numerical contract: encoder conv accumulation is a SINGLE
// sequential FMA chain per output in ascending k with k flattened as
// (ky, kx, c) — c fastest — to bit-match XLA-CPU/Eigen's im2col GEMM and
// keep the top-k selection identical to the reference.
// ---------------------------------------------------------------------------

#define NIMG 64
#define F    512
#define OHW  28
#define NPIX (NIMG*OHW*OHW)      // 50176
#define COUT 128
#define OUTN ((size_t)NPIX*COUT) // 6422528
#define BN_EPS 1e-5f

// ------------------------- device scratch (static) -------------------------
__device__ float g_a[(size_t)NPIX*F];       // encoder activations [pix][F]
__device__ float g_spval[NPIX*32];
__device__ int   g_spidx[NPIX*32];
__device__ int   g_spcnt[NPIX];
__device__ float g_out0[OUTN];              // layer0 output (pre then normalized)
__device__ float g_p1[OUTN];                // layer1 proj pre-BN
__device__ float g_psc[OUTN];               // shortcut pre-BN
__device__ float g_wT[1152*512];            // enc weights [k=(ky,kx,c)][F]
__device__ float g_wr[9*512*128];           // enc weights [kykx][F][C] for recon
__device__ float g_wpT[512*128];            // proj weights [F][COUT]
__device__ float g_wscT[64*128];            // shortcut weights [C][COUT]
__device__ float g_partial[NPIX];           // block partial sums (aux)
__device__ float g_mean[3][128];            // BN mean per slot {out0, p1, sc}
__device__ float g_rstd[3][128];            // BN rsqrt(var+eps) per slot

// ------------------------- weight re-layouts -------------------------------
// g_wT[k][f] with k = ky*3*CIN + kx*CIN + c  (c fastest -> Eigen patch order)
__global__ void transpose_wenc(const float* __restrict__ w, int CIN) {
    int K = CIN * 9;
    int i = blockIdx.x * 256 + threadIdx.x;
    if (i >= K * 512) return;
    int k = i / 512, f = i - k * 512;
    int ky = k / (3 * CIN);
    int r  = k - ky * 3 * CIN;
    int kx = r / CIN;
    int c  = r - kx * CIN;
    g_wT[i] = w[(f * CIN + c) * 9 + ky * 3 + kx];
}
__global__ void make_wr(const float* __restrict__ w, int CIN) {
    int tot = 9 * 512 * CIN;
    int i = blockIdx.x * 256 + threadIdx.x;
    if (i >= tot) return;
    int c = i % CIN;
    int f = (i / CIN) % 512;
    int r = i / (CIN * 512);
    g_wr[i] = w[(f * CIN + c) * 9 + r];
}
__global__ void make_wpT(const float* __restrict__ wp) {
    int i = blockIdx.x * 256 + threadIdx.x;
    if (i >= 512 * 128) return;
    int f = i / 128, co = i - f * 128;
    g_wpT[i] = wp[co * 512 + f];
}
__global__ void make_wscT(const float* __restrict__ w) {
    int i = blockIdx.x * 256 + threadIdx.x;
    if (i >= 64 * 128) return;
    int c = i / 128, co = i - c * 128;
    g_wscT[i] = w[co * 64 + c];
}

// ------------------------- encoder conv (implicit GEMM) --------------------
// Output a[pix][F].  Tile: BM=128 pixels x BN=64 filters x BK=16, 256 thr,
// microtile 8x4.  k flattened as (ky,kx,c), accumulated strictly ascending
// with one fmaf chain per output.
template<int CIN, int STRIDE, int HIN, bool IN0>
__global__ void __launch_bounds__(256) conv_enc(const float* __restrict__ xin) {
    const int K = CIN * 9;
    const float* __restrict__ src = IN0 ? (const float*)g_out0 : xin;

    __shared__ float As[16][128];
    __shared__ float Bs[16][64];
    __shared__ int   sBase[128];
    __shared__ int   sOy[128];
    __shared__ int   sOx[128];

    int tid = threadIdx.x;
    int bm = blockIdx.x, bn = blockIdx.y;

    if (tid < 128) {
        int p = bm * 128 + tid;
        int n = p / 784;
        int r = p - n * 784;
        int oy = r / 28, ox = r - oy * 28;
        sOy[tid] = oy * STRIDE;
        sOx[tid] = ox * STRIDE;
        sBase[tid] = n * CIN * HIN * HIN + oy * STRIDE * HIN + ox * STRIDE;
    }
    __syncthreads();

    int m = tid & 127;           // A-load pixel
    int fb = tid & 63;           // B-load filter
    int ty = tid >> 4;           // 0..15 -> 8 pixel rows
    int tx = tid & 15;           // 0..15 -> 4 filter cols
    int base_m = sBase[m], oyS = sOy[m], oxS = sOx[m];

    float acc[8][4];
#pragma unroll
    for (int i = 0; i < 8; i++)
#pragma unroll
        for (int j = 0; j < 4; j++) acc[i][j] = 0.f;

    for (int kt = 0; kt < K; kt += 16) {
        // A tile: 16x128, 8 elems/thread.  k = (ky,kx,c), c fastest.
#pragma unroll
        for (int j = 0; j < 8; j++) {
            int kl = j * 2 + (tid >> 7);
            int k = kt + kl;
            int ky = k / (3 * CIN);
            int rr = k - ky * 3 * CIN;
            int kx = rr / CIN;
            int c  = rr - kx * CIN;
            int iy = oyS + ky - 1, ix = oxS + kx - 1;
            float v = 0.f;
            if ((unsigned)iy < (unsigned)HIN && (unsigned)ix < (unsigned)HIN)
                v = src[base_m + c * HIN * HIN + (ky - 1) * HIN + (kx - 1)];
            As[kl][m] = v;
        }
        // B tile: 16x64, 4 elems/thread
#pragma unroll
        for (int j = 0; j < 4; j++) {
            int kl = j * 4 + (tid >> 6);
            Bs[kl][fb] = g_wT[(kt + kl) * F + bn * 64 + fb];
        }
        __syncthreads();

#pragma unroll
        for (int kk = 0; kk < 16; kk++) {
            float4 a0 = *(const float4*)&As[kk][ty * 8];
            float4 a1 = *(const float4*)&As[kk][ty * 8 + 4];
            float4 b4 = *(const float4*)&Bs[kk][tx * 4];
            float av[8] = {a0.x, a0.y, a0.z, a0.w, a1.x, a1.y, a1.z, a1.w};
            float bv[4] = {b4.x, b4.y, b4.z, b4.w};
#pragma unroll
            for (int i = 0; i < 8; i++)
#pragma unroll
                for (int j = 0; j < 4; j++)
                    acc[i][j] = fmaf(av[i], bv[j], acc[i][j]);
        }
        __syncthreads();
    }

    int f0 = bn * 64 + tx * 4;
#pragma unroll
    for (int i = 0; i < 8; i++) {
        int pix = bm * 128 + ty * 8 + i;
        float4 o = {acc[i][0], acc[i][1], acc[i][2], acc[i][3]};
        *(float4*)&g_a[(size_t)pix * F + f0] = o;
    }
}

// ------------------------- exact top-k (with tie semantics) ----------------
__global__ void __launch_bounds__(256) topk_kernel() {
    int warp = blockIdx.x * 8 + (threadIdx.x >> 5);
    int lane = threadIdx.x & 31;
    if (warp >= NPIX) return;
    const float* ap = g_a + (size_t)warp * F;

    float v[16];
#pragma unroll
    for (int j = 0; j < 16; j++) v[j] = ap[j * 32 + lane];

    unsigned alive = 0xFFFFu;
    int removed = 0;
    float T = -3.4e38f;
    for (int it = 0; it < 16; it++) {
        float lm = -3.4e38f;
#pragma unroll
        for (int j = 0; j < 16; j++)
            if (alive & (1u << j)) lm = fmaxf(lm, v[j]);
#pragma unroll
        for (int o = 16; o > 0; o >>= 1)
            lm = fmaxf(lm, __shfl_xor_sync(0xffffffffu, lm, o));
        unsigned em = 0; int c = 0;
#pragma unroll
        for (int j = 0; j < 16; j++)
            if ((alive & (1u << j)) && v[j] == lm) { em |= 1u << j; c++; }
#pragma unroll
        for (int o = 16; o > 0; o >>= 1)
            c += __shfl_xor_sync(0xffffffffu, c, o);
        T = lm;
        if (removed + c >= 16) break;
        removed += c;
        alive &= ~em;
    }

    int base = 0;
#pragma unroll
    for (int j = 0; j < 16; j++) {
        bool keep = v[j] >= T;
        unsigned bal = __ballot_sync(0xffffffffu, keep);
        if (keep) {
            int pos = base + __popc(bal & ((1u << lane) - 1u));
            if (pos < 32) {
                g_spidx[warp * 32 + pos] = j * 32 + lane;
                g_spval[warp * 32 + pos] = v[j];
            }
        }
        base += __popc(bal);
    }
    if (lane == 0) g_spcnt[warp] = base < 32 ? base : 32;
}

// ------------------------- sparse adjoint recon + aux ----------------------
template<int CIN, int STRIDE, int HIN, bool REF0>
__global__ void __launch_bounds__(256) recon_aux_kernel(const float* __restrict__ refp) {
    const int PPB = 256 / CIN;
    int tid = threadIdx.x;
    int c = tid % CIN;
    int pi = tid / CIN;
    int g = blockIdx.x * PPB + pi;
    int n = g / (HIN * HIN);
    int r = g - n * (HIN * HIN);
    int y = r / HIN, xx = r - y * HIN;

    float recon = 0.f;
#pragma unroll
    for (int ky = 0; ky < 3; ky++) {
        int t = y + 1 - ky;
        int oy;
        if (STRIDE == 2) { if (t & 1) continue; oy = t >> 1; } else oy = t;
        if ((unsigned)oy >= 28u) continue;
#pragma unroll
        for (int kx = 0; kx < 3; kx++) {
            int s = xx + 1 - kx;
            int ox;
            if (STRIDE == 2) { if (s & 1) continue; ox = s >> 1; } else ox = s;
            if ((unsigned)ox >= 28u) continue;
            int q = (n * 28 + oy) * 28 + ox;
            int cnt = g_spcnt[q];
            const float* wb = g_wr + (size_t)(ky * 3 + kx) * F * CIN;
            for (int e = 0; e < cnt; e++) {
                int fidx = g_spidx[q * 32 + e];
                float val = g_spval[q * 32 + e];
                recon += val * wb[fidx * CIN + c];
            }
        }
    }
    size_t ridx = ((size_t)(n * CIN + c) * HIN + y) * HIN + xx;
    float refv = REF0 ? g_out0[ridx] : refp[ridx];
    float d = recon - refv;

    __shared__ float red[256];
    red[tid] = d * d;
    __syncthreads();
    for (int st = 128; st > 0; st >>= 1) {
        if (tid < st) red[tid] += red[tid + st];
        __syncthreads();
    }
    if (tid == 0) g_partial[blockIdx.x] = red[0];
}

__global__ void reduce_partials(int n, float scale, float* __restrict__ out) {
    __shared__ float red[256];
    float s = 0.f;
    for (int i = threadIdx.x; i < n; i += 256) s += g_partial[i];
    red[threadIdx.x] = s;
    __syncthreads();
    for (int st = 128; st > 0; st >>= 1) {
        if (threadIdx.x < st) red[threadIdx.x] += red[threadIdx.x + st];
        __syncthreads();
    }
    if (threadIdx.x == 0) *out = red[0] * scale;
}

// ------------------------- sparse 1x1 projection ---------------------------
__global__ void __launch_bounds__(256) proj_kernel(int slot) {
    float* out = (slot == 0) ? g_out0 : g_p1;
    int tid = threadIdx.x;
    int co = tid & 127;
    int pi = tid >> 7;
    int q = blockIdx.x * 2 + pi;
    int cnt = g_spcnt[q];
    float acc = 0.f;
    for (int e = 0; e < cnt; e++) {
        int f = g_spidx[q * 32 + e];
        acc += g_spval[q * 32 + e] * g_wpT[f * COUT + co];
    }
    int n = q / 784, r = q - n * 784;
    out[(size_t)(n * COUT + co) * 784 + r] = acc;
}

// ------------------------- shortcut 1x1 stride-2 ---------------------------
__global__ void __launch_bounds__(256) shortcut_kernel(const float* __restrict__ x) {
    int tid = threadIdx.x;
    int co = tid & 127;
    int pi = tid >> 7;
    int q = blockIdx.x * 2 + pi;
    int n = q / 784, r = q - n * 784;
    int oy = r / 28, ox = r - oy * 28;
    const float* xp = x + (size_t)n * 64 * 3136 + (2 * oy) * 56 + 2 * ox;
    float acc = 0.f;
#pragma unroll
    for (int c = 0; c < 64; c++) acc = fmaf(xp[c * 3136], g_wscT[c * 128 + co], acc);
    g_psc[(size_t)(n * COUT + co) * 784 + r] = acc;
}

// ------------------------- batchnorm (training stats, double-precision) ----
__global__ void __launch_bounds__(256) bn_stats_kernel(int slot) {
    const float* src = (slot == 0) ? g_out0 : (slot == 1 ? g_p1 : g_psc);
    int co = blockIdx.x;
    int tid = threadIdx.x;
    double s = 0.0, s2 = 0.0;
    for (int n = 0; n < NIMG; n++) {
        const float* row = src + (size_t)(n * COUT + co) * 784;
        for (int r = tid; r < 784; r += 256) {
            double v = (double)row[r];
            s += v; s2 += v * v;
        }
    }
    __shared__ double rs[256], rq[256];
    rs[tid] = s; rq[tid] = s2;
    __syncthreads();
    for (int st = 128; st > 0; st >>= 1) {
        if (tid < st) { rs[tid] += rs[tid + st]; rq[tid] += rq[tid + st]; }
        __syncthreads();
    }
    if (tid == 0) {
        double mean = rs[0] * (1.0 / 50176.0);
        double var = rq[0] * (1.0 / 50176.0) - mean * mean;
        g_mean[slot][co] = (float)mean;
        g_rstd[slot][co] = rsqrtf((float)var + BN_EPS);
    }
}

// apply in reference op order: ((x-m)*r)*g + b
__global__ void __launch_bounds__(256) norm0_kernel(const float* __restrict__ gg,
                                                    const float* __restrict__ bb) {
    size_t i = (size_t)blockIdx.x * 256 + threadIdx.x;
    if (i >= OUTN) return;
    int co = (int)((i / 784) & 127);
    g_out0[i] = ((g_out0[i] - g_mean[0][co]) * g_rstd[0][co]) * gg[co] + bb[co];
}

__global__ void __launch_bounds__(256) final_kernel(float* __restrict__ dout,
        const float* __restrict__ g1, const float* __restrict__ b1,
        const float* __restrict__ gsc, const float* __restrict__ bsc) {
    size_t i = (size_t)blockIdx.x * 256 + threadIdx.x;
    if (i >= OUTN) return;
    int co = (int)((i / 784) & 127);
    float v1 = ((g_p1[i]  - g_mean[1][co]) * g_rstd[1][co]) * g1[co]  + b1[co];
    float v2 = ((g_psc[i] - g_mean[2][co]) * g_rstd[2][co]) * gsc[co] + bsc[co];
    float v = v1 + v2;
    dout[i] = v > 0.f ? v : 0.f;
}

// ---------------------------------------------------------------------------
extern "C" void kernel_launch(void* const* d_in, const int* in_sizes, int n_in,
                              void* d_out, int out_size) {
    const float* x       = (const float*)d_in[0];
    const float* w_enc0  = (const float*)d_in[1];
    const float* w_proj0 = (const float*)d_in[2];
    const float* g0      = (const float*)d_in[3];
    const float* b0      = (const float*)d_in[4];
    const float* w_enc1  = (const float*)d_in[5];
    const float* w_proj1 = (const float*)d_in[6];
    const float* g1      = (const float*)d_in[7];
    const float* b1      = (const float*)d_in[8];
    const float* w_sc    = (const float*)d_in[9];
    const float* g_sc    = (const float*)d_in[10];
    const float* b_sc    = (const float*)d_in[11];
    float* out = (float*)d_out;

    const int elem_blocks = (int)((OUTN + 255) / 256);

    // ---------------- layer 0 ----------------
    transpose_wenc<<<(576 * 512 + 255) / 256, 256>>>(w_enc0, 64);
    conv_enc<64, 2, 56, false><<<dim3(NPIX / 128, F / 64), 256>>>(x);
    topk_kernel<<<NPIX / 8, 256>>>();
    make_wr<<<(9 * 512 * 64 + 255) / 256, 256>>>(w_enc0, 64);
    recon_aux_kernel<64, 2, 56, false><<<NIMG * 3136 / 4, 256>>>(x);
    reduce_partials<<<1, 256>>>(NIMG * 3136 / 4, 1.f / 12845056.f, out + out_size - 2);
    make_wpT<<<(512 * 128 + 255) / 256, 256>>>(w_proj0);
    proj_kernel<<<NPIX / 2, 256>>>(0);
    bn_stats_kernel<<<128, 256>>>(0);
    norm0_kernel<<<elem_blocks, 256>>>(g0, b0);

    // ---------------- layer 1 ----------------
    transpose_wenc<<<(1152 * 512 + 255) / 256, 256>>>(w_enc1, 128);
    conv_enc<128, 1, 28, true><<<dim3(NPIX / 128, F / 64), 256>>>(x);
    topk_kernel<<<NPIX / 8, 256>>>();
    make_wr<<<(9 * 512 * 128 + 255) / 256, 256>>>(w_enc1, 128);
    recon_aux_kernel<128, 1, 28, true><<<NIMG * 784 / 2, 256>>>(nullptr);
    reduce_partials<<<1, 256>>>(NIMG * 784 / 2, 1.f / 6422528.f, out + out_size - 1);
    make_wpT<<<(512 * 128 + 255) / 256, 256>>>(w_proj1);
    proj_kernel<<<NPIX / 2, 256>>>(1);
    bn_stats_kernel<<<128, 256>>>(1);

    // ---------------- shortcut + fuse ----------------
    make_wscT<<<(64 * 128 + 255) / 256, 256>>>(w_sc);
    shortcut_kernel<<<NPIX / 2, 256>>>(x);
    bn_stats_kernel<<<128, 256>>>(2);
    final_kernel<<<elem_blocks, 256>>>(out, g1, b1, g_sc, b_sc);
}

// round 3
// speedup vs baseline: 1.0835x; 1.0835x over previous
#include <cuda_runtime.h>
#include <cstdint>

// ---------------------------------------------------------------------------
// BasicBlock_Sparse: two sparse-coding layers + shortcut, fp32.
//   layer0: conv3x3 s2 (64->512), topk16, adjoint-recon aux, 1x1 proj (512->128), BN
//   layer1: conv3x3 s1 (128->512), topk16, adjoint-recon aux, 1x1 proj, BN
//   shortcut: 1x1 s2 (64->128), BN;  out = relu(l1 + sc)
//
// NUMERICAL CONTRACT: encoder conv accumulation is a SINGLE sequential FMA
// chain per output, ascending k = (ky, kx, c) with c fastest (bit-matches
// XLA-CPU/Eigen im2col GEMM -> identical top-k selection). fma.rn.f32x2
// performs two independent IEEE fmas, so packing two outputs per register
// preserves each chain bit-exactly while doubling fp32 throughput.
// ---------------------------------------------------------------------------

#define NIMG 64
#define F    512
#define OHW  28
#define NPIX (NIMG*OHW*OHW)      // 50176
#define COUT 128
#define OUTN ((size_t)NPIX*COUT) // 6422528
#define BN_EPS 1e-5f

typedef unsigned long long u64;

// ------------------------- device scratch (static) -------------------------
__device__ float g_a[(size_t)NPIX*F];       // encoder activations [pix][F]
__device__ float g_spval[NPIX*32];
__device__ int   g_spidx[NPIX*32];
__device__ int   g_spcnt[NPIX];
__device__ float g_out0[OUTN];              // layer0 output (pre then normalized)
__device__ float g_p1[OUTN];                // layer1 proj pre-BN
__device__ float g_psc[OUTN];               // shortcut pre-BN
__device__ float g_wT[1152*512];            // enc weights [k=(ky,kx,c)][F]
__device__ float g_wr[9*512*128];           // enc weights [kykx][F][C] for recon
__device__ float g_wpT[512*128];            // proj weights [F][COUT]
__device__ float g_wscT[64*128];            // shortcut weights [C][COUT]
__device__ float g_partial[NPIX];           // block partial sums (aux)
__device__ float g_mean[3][128];            // BN mean per slot {out0, p1, sc}
__device__ float g_rstd[3][128];            // BN rsqrt(var+eps) per slot

// ------------------------- f32x2 helpers -----------------------------------
__device__ __forceinline__ void ffma2(u64& d, u64 a, u64 b) {
    asm("fma.rn.f32x2 %0, %1, %2, %0;" : "+l"(d) : "l"(a), "l"(b));
}
__device__ __forceinline__ u64 dup2(float x) {
    u64 r;
    unsigned xi = __float_as_uint(x);
    asm("mov.b64 %0, {%1, %1};" : "=l"(r) : "r"(xi));
    return r;
}
__device__ __forceinline__ void unpack2(u64 v, float& lo, float& hi) {
    unsigned a, b;
    asm("mov.b64 {%0, %1}, %2;" : "=r"(a), "=r"(b) : "l"(v));
    lo = __uint_as_float(a);
    hi = __uint_as_float(b);
}

// ------------------------- weight re-layouts -------------------------------
// g_wT[k][f] with k = ky*3*CIN + kx*CIN + c  (c fastest -> Eigen patch order)
__global__ void transpose_wenc(const float* __restrict__ w, int CIN) {
    int K = CIN * 9;
    int i = blockIdx.x * 256 + threadIdx.x;
    if (i >= K * 512) return;
    int k = i / 512, f = i - k * 512;
    int ky = k / (3 * CIN);
    int r  = k - ky * 3 * CIN;
    int kx = r / CIN;
    int c  = r - kx * CIN;
    g_wT[i] = w[(f * CIN + c) * 9 + ky * 3 + kx];
}
__global__ void make_wr(const float* __restrict__ w, int CIN) {
    int tot = 9 * 512 * CIN;
    int i = blockIdx.x * 256 + threadIdx.x;
    if (i >= tot) return;
    int c = i % CIN;
    int f = (i / CIN) % 512;
    int r = i / (CIN * 512);
    g_wr[i] = w[(f * CIN + c) * 9 + r];
}
__global__ void make_wpT(const float* __restrict__ wp) {
    int i = blockIdx.x * 256 + threadIdx.x;
    if (i >= 512 * 128) return;
    int f = i / 128, co = i - f * 128;
    g_wpT[i] = wp[co * 512 + f];
}
__global__ void make_wscT(const float* __restrict__ w) {
    int i = blockIdx.x * 256 + threadIdx.x;
    if (i >= 64 * 128) return;
    int c = i / 128, co = i - c * 128;
    g_wscT[i] = w[co * 64 + c];
}

// ------------------------- encoder conv (implicit GEMM, f32x2) -------------
// Tile: BM=128 pixels x BN=128 filters x BK=16, 256 thr, microtile 8x8.
// Filter pairs packed in f32x2; sequential ascending-k chain per output.
template<int CIN, int STRIDE, int HIN, bool IN0>
__global__ void __launch_bounds__(256, 2) conv_enc(const float* __restrict__ xin) {
    const int K = CIN * 9;
    const int NT = K / 16;
    const float* __restrict__ src = IN0 ? (const float*)g_out0 : xin;

    __shared__ float As[2][16][128];
    __shared__ float Bs[2][16][128];
    __shared__ int   sBase[128];
    __shared__ int   sOy[128];
    __shared__ int   sOx[128];

    int tid = threadIdx.x;
    int bm = blockIdx.x, bn = blockIdx.y;

    if (tid < 128) {
        int p = bm * 128 + tid;
        int n = p / 784;
        int r = p - n * 784;
        int oy = r / 28, ox = r - oy * 28;
        sOy[tid] = oy * STRIDE;
        sOx[tid] = ox * STRIDE;
        sBase[tid] = n * CIN * HIN * HIN + oy * STRIDE * HIN + ox * STRIDE;
    }
    __syncthreads();

    // loader mapping
    int m  = tid & 127;          // A pixel / B filter column
    int half = tid >> 7;         // 0/1 -> kl parity
    int base_m = sBase[m], oyS = sOy[m], oxS = sOx[m];

    // compute mapping: 16x16 threads, each 8 pixels x 8 filters (4 pairs)
    int trow = tid >> 4;         // 0..15 -> pixel group
    int tcol = tid & 15;         // 0..15 -> filter group

    u64 acc[8][4];
#pragma unroll
    for (int i = 0; i < 8; i++)
#pragma unroll
        for (int j = 0; j < 4; j++) acc[i][j] = 0ULL;

    float pa[8], pb[8];

    // ---- prefetch tile 0 ----
    {
        int kt = 0;
        int ky = kt / (3 * CIN);
        int rr = kt - ky * 3 * CIN;
        int kx = rr / CIN;
        int c0 = rr - kx * CIN;
        int iy = oyS + ky - 1, ix = oxS + kx - 1;
        bool valid = ((unsigned)iy < (unsigned)HIN) && ((unsigned)ix < (unsigned)HIN);
        const float* ap = src + base_m + (ky - 1) * HIN + (kx - 1);
#pragma unroll
        for (int j = 0; j < 8; j++) {
            int kl = j * 2 + half;
            pa[j] = valid ? ap[(c0 + kl) * HIN * HIN] : 0.f;
            pb[j] = g_wT[(kt + kl) * F + bn * 128 + m];
        }
#pragma unroll
        for (int j = 0; j < 8; j++) {
            int kl = j * 2 + half;
            As[0][kl][m] = pa[j];
            Bs[0][kl][m] = pb[j];
        }
        __syncthreads();
    }

    for (int t = 0; t < NT; t++) {
        // prefetch next tile into regs (gmem latency overlapped with compute)
        if (t + 1 < NT) {
            int kt = (t + 1) * 16;
            int ky = kt / (3 * CIN);
            int rr = kt - ky * 3 * CIN;
            int kx = rr / CIN;
            int c0 = rr - kx * CIN;
            int iy = oyS + ky - 1, ix = oxS + kx - 1;
            bool valid = ((unsigned)iy < (unsigned)HIN) && ((unsigned)ix < (unsigned)HIN);
            const float* ap = src + base_m + (ky - 1) * HIN + (kx - 1);
#pragma unroll
            for (int j = 0; j < 8; j++) {
                int kl = j * 2 + half;
                pa[j] = valid ? ap[(c0 + kl) * HIN * HIN] : 0.f;
                pb[j] = g_wT[(kt + kl) * F + bn * 128 + m];
            }
        }

        int cur = t & 1;
#pragma unroll
        for (int kk = 0; kk < 16; kk++) {
            const float4* a4 = reinterpret_cast<const float4*>(&As[cur][kk][trow * 8]);
            float4 a0 = a4[0];
            float4 a1 = a4[1];
            const ulonglong2* b2 = reinterpret_cast<const ulonglong2*>(&Bs[cur][kk][tcol * 8]);
            ulonglong2 b01 = b2[0];
            ulonglong2 b23 = b2[1];
            u64 bb[4] = {b01.x, b01.y, b23.x, b23.y};
            u64 ad[8] = {dup2(a0.x), dup2(a0.y), dup2(a0.z), dup2(a0.w),
                         dup2(a1.x), dup2(a1.y), dup2(a1.z), dup2(a1.w)};
#pragma unroll
            for (int i = 0; i < 8; i++)
#pragma unroll
                for (int j = 0; j < 4; j++)
                    ffma2(acc[i][j], ad[i], bb[j]);
        }

        if (t + 1 < NT) {
            __syncthreads();   // reads of buffer (t+1)&1 (iter t-1) complete
            int nxt = (t + 1) & 1;
#pragma unroll
            for (int j = 0; j < 8; j++) {
                int kl = j * 2 + half;
                As[nxt][kl][m] = pa[j];
                Bs[nxt][kl][m] = pb[j];
            }
            __syncthreads();
        }
    }

    // epilogue: unpack pairs, store float4 x2 per pixel row
    int f0 = bn * 128 + tcol * 8;
#pragma unroll
    for (int i = 0; i < 8; i++) {
        int pix = bm * 128 + trow * 8 + i;
        float4 o0, o1;
        unpack2(acc[i][0], o0.x, o0.y);
        unpack2(acc[i][1], o0.z, o0.w);
        unpack2(acc[i][2], o1.x, o1.y);
        unpack2(acc[i][3], o1.z, o1.w);
        float* dst = &g_a[(size_t)pix * F + f0];
        *(float4*)dst = o0;
        *(float4*)(dst + 4) = o1;
    }
}

// ------------------------- exact top-k (with tie semantics) ----------------
__global__ void __launch_bounds__(256) topk_kernel() {
    int warp = blockIdx.x * 8 + (threadIdx.x >> 5);
    int lane = threadIdx.x & 31;
    if (warp >= NPIX) return;
    const float* ap = g_a + (size_t)warp * F;

    float v[16];
#pragma unroll
    for (int j = 0; j < 16; j++) v[j] = ap[j * 32 + lane];

    unsigned alive = 0xFFFFu;
    int removed = 0;
    float T = -3.4e38f;
    for (int it = 0; it < 16; it++) {
        float lm = -3.4e38f;
#pragma unroll
        for (int j = 0; j < 16; j++)
            if (alive & (1u << j)) lm = fmaxf(lm, v[j]);
#pragma unroll
        for (int o = 16; o > 0; o >>= 1)
            lm = fmaxf(lm, __shfl_xor_sync(0xffffffffu, lm, o));
        unsigned em = 0; int c = 0;
#pragma unroll
        for (int j = 0; j < 16; j++)
            if ((alive & (1u << j)) && v[j] == lm) { em |= 1u << j; c++; }
#pragma unroll
        for (int o = 16; o > 0; o >>= 1)
            c += __shfl_xor_sync(0xffffffffu, c, o);
        T = lm;
        if (removed + c >= 16) break;
        removed += c;
        alive &= ~em;
    }

    int base = 0;
#pragma unroll
    for (int j = 0; j < 16; j++) {
        bool keep = v[j] >= T;
        unsigned bal = __ballot_sync(0xffffffffu, keep);
        if (keep) {
            int pos = base + __popc(bal & ((1u << lane) - 1u));
            if (pos < 32) {
                g_spidx[warp * 32 + pos] = j * 32 + lane;
                g_spval[warp * 32 + pos] = v[j];
            }
        }
        base += __popc(bal);
    }
    if (lane == 0) g_spcnt[warp] = base < 32 ? base : 32;
}

// ------------------------- sparse adjoint recon + aux ----------------------
template<int CIN, int STRIDE, int HIN, bool REF0>
__global__ void __launch_bounds__(256) recon_aux_kernel(const float* __restrict__ refp) {
    const int PPB = 256 / CIN;
    int tid = threadIdx.x;
    int c = tid % CIN;
    int pi = tid / CIN;
    int g = blockIdx.x * PPB + pi;
    int n = g / (HIN * HIN);
    int r = g - n * (HIN * HIN);
    int y = r / HIN, xx = r - y * HIN;

    float recon = 0.f;
#pragma unroll
    for (int ky = 0; ky < 3; ky++) {
        int t = y + 1 - ky;
        int oy;
        if (STRIDE == 2) { if (t & 1) continue; oy = t >> 1; } else oy = t;
        if ((unsigned)oy >= 28u) continue;
#pragma unroll
        for (int kx = 0; kx < 3; kx++) {
            int s = xx + 1 - kx;
            int ox;
            if (STRIDE == 2) { if (s & 1) continue; ox = s >> 1; } else ox = s;
            if ((unsigned)ox >= 28u) continue;
            int q = (n * 28 + oy) * 28 + ox;
            int cnt = g_spcnt[q];
            const float* wb = g_wr + (size_t)(ky * 3 + kx) * F * CIN;
            for (int e = 0; e < cnt; e++) {
                int fidx = g_spidx[q * 32 + e];
                float val = g_spval[q * 32 + e];
                recon += val * wb[fidx * CIN + c];
            }
        }
    }
    size_t ridx = ((size_t)(n * CIN + c) * HIN + y) * HIN + xx;
    float refv = REF0 ? g_out0[ridx] : refp[ridx];
    float d = recon - refv;

    __shared__ float red[256];
    red[tid] = d * d;
    __syncthreads();
    for (int st = 128; st > 0; st >>= 1) {
        if (tid < st) red[tid] += red[tid + st];
        __syncthreads();
    }
    if (tid == 0) g_partial[blockIdx.x] = red[0];
}

__global__ void reduce_partials(int n, float scale, float* __restrict__ out) {
    __shared__ float red[256];
    float s = 0.f;
    for (int i = threadIdx.x; i < n; i += 256) s += g_partial[i];
    red[threadIdx.x] = s;
    __syncthreads();
    for (int st = 128; st > 0; st >>= 1) {
        if (threadIdx.x < st) red[threadIdx.x] += red[threadIdx.x + st];
        __syncthreads();
    }
    if (threadIdx.x == 0) *out = red[0] * scale;
}

// ------------------------- sparse 1x1 projection ---------------------------
__global__ void __launch_bounds__(256) proj_kernel(int slot) {
    float* out = (slot == 0) ? g_out0 : g_p1;
    int tid = threadIdx.x;
    int co = tid & 127;
    int pi = tid >> 7;
    int q = blockIdx.x * 2 + pi;
    int cnt = g_spcnt[q];
    float acc = 0.f;
    for (int e = 0; e < cnt; e++) {
        int f = g_spidx[q * 32 + e];
        acc += g_spval[q * 32 + e] * g_wpT[f * COUT + co];
    }
    int n = q / 784, r = q - n * 784;
    out[(size_t)(n * COUT + co) * 784 + r] = acc;
}

// ------------------------- shortcut 1x1 stride-2 ---------------------------
__global__ void __launch_bounds__(256) shortcut_kernel(const float* __restrict__ x) {
    int tid = threadIdx.x;
    int co = tid & 127;
    int pi = tid >> 7;
    int q = blockIdx.x * 2 + pi;
    int n = q / 784, r = q - n * 784;
    int oy = r / 28, ox = r - oy * 28;
    const float* xp = x + (size_t)n * 64 * 3136 + (2 * oy) * 56 + 2 * ox;
    float acc = 0.f;
#pragma unroll
    for (int c = 0; c < 64; c++) acc = fmaf(xp[c * 3136], g_wscT[c * 128 + co], acc);
    g_psc[(size_t)(n * COUT + co) * 784 + r] = acc;
}

// ------------------------- batchnorm (training stats, double-precision) ----
__global__ void __launch_bounds__(256) bn_stats_kernel(int slot) {
    const float* src = (slot == 0) ? g_out0 : (slot == 1 ? g_p1 : g_psc);
    int co = blockIdx.x;
    int tid = threadIdx.x;
    double s = 0.0, s2 = 0.0;
    for (int n = 0; n < NIMG; n++) {
        const float* row = src + (size_t)(n * COUT + co) * 784;
        for (int r = tid; r < 784; r += 256) {
            double v = (double)row[r];
            s += v; s2 += v * v;
        }
    }
    __shared__ double rs[256], rq[256];
    rs[tid] = s; rq[tid] = s2;
    __syncthreads();
    for (int st = 128; st > 0; st >>= 1) {
        if (tid < st) { rs[tid] += rs[tid + st]; rq[tid] += rq[tid + st]; }
        __syncthreads();
    }
    if (tid == 0) {
        double mean = rs[0] * (1.0 / 50176.0);
        double var = rq[0] * (1.0 / 50176.0) - mean * mean;
        g_mean[slot][co] = (float)mean;
        g_rstd[slot][co] = rsqrtf((float)var + BN_EPS);
    }
}

// apply in reference op order: ((x-m)*r)*g + b
__global__ void __launch_bounds__(256) norm0_kernel(const float* __restrict__ gg,
                                                    const float* __restrict__ bb) {
    size_t i = (size_t)blockIdx.x * 256 + threadIdx.x;
    if (i >= OUTN) return;
    int co = (int)((i / 784) & 127);
    g_out0[i] = ((g_out0[i] - g_mean[0][co]) * g_rstd[0][co]) * gg[co] + bb[co];
}

__global__ void __launch_bounds__(256) final_kernel(float* __restrict__ dout,
        const float* __restrict__ g1, const float* __restrict__ b1,
        const float* __restrict__ gsc, const float* __restrict__ bsc) {
    size_t i = (size_t)blockIdx.x * 256 + threadIdx.x;
    if (i >= OUTN) return;
    int co = (int)((i / 784) & 127);
    float v1 = ((g_p1[i]  - g_mean[1][co]) * g_rstd[1][co]) * g1[co]  + b1[co];
    float v2 = ((g_psc[i] - g_mean[2][co]) * g_rstd[2][co]) * gsc[co] + bsc[co];
    float v = v1 + v2;
    dout[i] = v > 0.f ? v : 0.f;
}

// ---------------------------------------------------------------------------
extern "C" void kernel_launch(void* const* d_in, const int* in_sizes, int n_in,
                              void* d_out, int out_size) {
    const float* x       = (const float*)d_in[0];
    const float* w_enc0  = (const float*)d_in[1];
    const float* w_proj0 = (const float*)d_in[2];
    const float* g0      = (const float*)d_in[3];
    const float* b0      = (const float*)d_in[4];
    const float* w_enc1  = (const float*)d_in[5];
    const float* w_proj1 = (const float*)d_in[6];
    const float* g1      = (const float*)d_in[7];
    const float* b1      = (const float*)d_in[8];
    const float* w_sc    = (const float*)d_in[9];
    const float* g_sc    = (const float*)d_in[10];
    const float* b_sc    = (const float*)d_in[11];
    float* out = (float*)d_out;

    const int elem_blocks = (int)((OUTN + 255) / 256);

    // ---------------- layer 0 ----------------
    transpose_wenc<<<(576 * 512 + 255) / 256, 256>>>(w_enc0, 64);
    conv_enc<64, 2, 56, false><<<dim3(NPIX / 128, 4), 256>>>(x);
    topk_kernel<<<NPIX / 8, 256>>>();
    make_wr<<<(9 * 512 * 64 + 255) / 256, 256>>>(w_enc0, 64);
    recon_aux_kernel<64, 2, 56, false><<<NIMG * 3136 / 4, 256>>>(x);
    reduce_partials<<<1, 256>>>(NIMG * 3136 / 4, 1.f / 12845056.f, out + out_size - 2);
    make_wpT<<<(512 * 128 + 255) / 256, 256>>>(w_proj0);
    proj_kernel<<<NPIX / 2, 256>>>(0);
    bn_stats_kernel<<<128, 256>>>(0);
    norm0_kernel<<<elem_blocks, 256>>>(g0, b0);

    // ---------------- layer 1 ----------------
    transpose_wenc<<<(1152 * 512 + 255) / 256, 256>>>(w_enc1, 128);
    conv_enc<128, 1, 28, true><<<dim3(NPIX / 128, 4), 256>>>(x);
    topk_kernel<<<NPIX / 8, 256>>>();
    make_wr<<<(9 * 512 * 128 + 255) / 256, 256>>>(w_enc1, 128);
    recon_aux_kernel<128, 1, 28, true><<<NIMG * 784 / 2, 256>>>(nullptr);
    reduce_partials<<<1, 256>>>(NIMG * 784 / 2, 1.f / 6422528.f, out + out_size - 1);
    make_wpT<<<(512 * 128 + 255) / 256, 256>>>(w_proj1);
    proj_kernel<<<NPIX / 2, 256>>>(1);
    bn_stats_kernel<<<128, 256>>>(1);

    // ---------------- shortcut + fuse ----------------
    make_wscT<<<(64 * 128 + 255) / 256, 256>>>(w_sc);
    shortcut_kernel<<<NPIX / 2, 256>>>(x);
    bn_stats_kernel<<<128, 256>>>(2);
    final_kernel<<<elem_blocks, 256>>>(out, g1, b1, g_sc, b_sc);
}

// round 4
// speedup vs baseline: 1.0872x; 1.0034x over previous
#include <cuda_runtime.h>
#include <cstdint>

// ---------------------------------------------------------------------------
// BasicBlock_Sparse: two sparse-coding layers + shortcut, fp32.
// NUMERICAL CONTRACT: encoder conv accumulation is a SINGLE sequential FMA
// chain per output, ascending k = (ky, kx, c) with c fastest (bit-matches
// XLA-CPU/Eigen im2col GEMM -> identical top-k selection). fma.rn.f32x2
// performs two independent IEEE fmas -> packing two filters per register
// preserves each chain bit-exactly.
// ---------------------------------------------------------------------------

#define NIMG 64
#define F    512
#define OHW  28
#define NPIX (NIMG*OHW*OHW)      // 50176
#define COUT 128
#define OUTN ((size_t)NPIX*COUT) // 6422528
#define BN_EPS 1e-5f

typedef unsigned long long u64;

// ------------------------- device scratch (static) -------------------------
__device__ float g_a[(size_t)NPIX*F];       // encoder activations [pix][F]
__device__ float g_spval[NPIX*32];
__device__ int   g_spidx[NPIX*32];
__device__ int   g_spcnt[NPIX];
__device__ float g_out0[OUTN];              // layer0 output (pre then normalized)
__device__ float g_p1[OUTN];                // layer1 proj pre-BN
__device__ float g_psc[OUTN];               // shortcut pre-BN
__device__ float g_wT0[576*512];            // enc0 weights [k=(ky,kx,c)][F]
__device__ float g_wT1[1152*512];           // enc1 weights [k][F]
__device__ float g_wr0[9*512*64];           // enc0 weights [kykx][F][C] for recon
__device__ float g_wr1[9*512*128];          // enc1 weights [kykx][F][C]
__device__ float g_wpT0[512*128];           // proj0 weights [F][COUT]
__device__ float g_wpT1[512*128];           // proj1 weights [F][COUT]
__device__ float g_wscT[64*128];            // shortcut weights [C][COUT]
__device__ float g_partial[NPIX];           // block partial sums (aux)
__device__ float g_mean[3][128];            // BN mean per slot {out0, p1, sc}
__device__ float g_rstd[3][128];            // BN rsqrt(var+eps) per slot

// ------------------------- asm helpers -------------------------------------
__device__ __forceinline__ void ffma2(u64& d, u64 a, u64 b) {
    asm("fma.rn.f32x2 %0, %1, %2, %0;" : "+l"(d) : "l"(a), "l"(b));
}
__device__ __forceinline__ u64 dup2(float x) {
    u64 r;
    unsigned xi = __float_as_uint(x);
    asm("mov.b64 %0, {%1, %1};" : "=l"(r) : "r"(xi));
    return r;
}
__device__ __forceinline__ void unpack2(u64 v, float& lo, float& hi) {
    unsigned a, b;
    asm("mov.b64 {%0, %1}, %2;" : "=r"(a), "=r"(b) : "l"(v));
    lo = __uint_as_float(a);
    hi = __uint_as_float(b);
}
__device__ __forceinline__ void cp4(unsigned dst, const float* src) {
    asm volatile("cp.async.ca.shared.global [%0], [%1], 4;" :: "r"(dst), "l"(src));
}
__device__ __forceinline__ void cp_commit() {
    asm volatile("cp.async.commit_group;");
}
__device__ __forceinline__ void cp_wait0() {
    asm volatile("cp.async.wait_group 0;");
}

// ------------------------- weight re-layouts -------------------------------
// wT[k][f] with k = ky*3*CIN + kx*CIN + c  (c fastest -> Eigen patch order)
__global__ void transpose_wenc(const float* __restrict__ w, int CIN, int which) {
    float* dst = which ? g_wT1 : g_wT0;
    int K = CIN * 9;
    int i = blockIdx.x * 256 + threadIdx.x;
    if (i >= K * 512) return;
    int k = i / 512, f = i - k * 512;
    int ky = k / (3 * CIN);
    int r  = k - ky * 3 * CIN;
    int kx = r / CIN;
    int c  = r - kx * CIN;
    dst[i] = w[(f * CIN + c) * 9 + ky * 3 + kx];
}
__global__ void make_wr(const float* __restrict__ w, int CIN, int which) {
    float* dst = which ? g_wr1 : g_wr0;
    int tot = 9 * 512 * CIN;
    int i = blockIdx.x * 256 + threadIdx.x;
    if (i >= tot) return;
    int c = i % CIN;
    int f = (i / CIN) % 512;
    int r = i / (CIN * 512);
    dst[i] = w[(f * CIN + c) * 9 + r];
}
__global__ void make_wpT(const float* __restrict__ wp, int which) {
    float* dst = which ? g_wpT1 : g_wpT0;
    int i = blockIdx.x * 256 + threadIdx.x;
    if (i >= 512 * 128) return;
    int f = i / 128, co = i - f * 128;
    dst[i] = wp[co * 512 + f];
}
__global__ void make_wscT(const float* __restrict__ w) {
    int i = blockIdx.x * 256 + threadIdx.x;
    if (i >= 64 * 128) return;
    int c = i / 128, co = i - c * 128;
    g_wscT[i] = w[co * 64 + c];
}

// ------------------------- encoder conv (implicit GEMM, f32x2) -------------
// Tile: BM=128 pixels x BN=128 filters x BK=16, 256 thr, microtile 8x8.
// cp.async double-buffered smem (no prefetch registers -> no spills).
template<int CIN, int STRIDE, int HIN, bool L1>
__global__ void __launch_bounds__(256, 2) conv_enc(const float* __restrict__ xin) {
    const int K = CIN * 9;
    const int NT = K / 16;
    const float* __restrict__ src = L1 ? (const float*)g_out0 : xin;
    const float* __restrict__ wT = L1 ? g_wT1 : g_wT0;

    __shared__ float As[2][16][128];
    __shared__ float Bs[2][16][128];
    __shared__ int   sBase[128];
    __shared__ int   sOy[128];
    __shared__ int   sOx[128];

    int tid = threadIdx.x;
    int bm = blockIdx.x, bn = blockIdx.y;

    if (tid < 128) {
        int p = bm * 128 + tid;
        int n = p / 784;
        int r = p - n * 784;
        int oy = r / 28, ox = r - oy * 28;
        sOy[tid] = oy * STRIDE;
        sOx[tid] = ox * STRIDE;
        sBase[tid] = n * CIN * HIN * HIN + oy * STRIDE * HIN + ox * STRIDE;
    }
    __syncthreads();

    // loader mapping: column m, rows j*2+half
    int m  = tid & 127;
    int half = tid >> 7;
    int base_m = sBase[m], oyS = sOy[m], oxS = sOx[m];

    unsigned aAddr = (unsigned)__cvta_generic_to_shared(&As[0][0][m]);
    unsigned bAddr = (unsigned)__cvta_generic_to_shared(&Bs[0][0][m]);
    const int bufStride = 16 * 128 * 4;       // bytes per buffer
    const int rowStride = 128 * 4;            // bytes per k-row

    // compute mapping: 16x16 threads, 8 pixels x 8 filters (4 f32x2 pairs)
    int trow = tid >> 4;
    int tcol = tid & 15;

    u64 acc[8][4];
#pragma unroll
    for (int i = 0; i < 8; i++)
#pragma unroll
        for (int j = 0; j < 4; j++) acc[i][j] = 0ULL;

    // tile loader: issues 16 x 4B cp.async (8 A + 8 B) for tile t into buf
    auto issue_tile = [&](int t, int buf) {
        int kt = t * 16;
        int ky = kt / (3 * CIN);
        int rr = kt - ky * 3 * CIN;
        int kx = rr / CIN;
        int c0 = rr - kx * CIN;
        int iy = oyS + ky - 1, ix = oxS + kx - 1;
        bool valid = ((unsigned)iy < (unsigned)HIN) && ((unsigned)ix < (unsigned)HIN);
        const float* ap = src + base_m + (ky - 1) * HIN + (kx - 1);
        const float* bp = wT + (size_t)kt * F + bn * 128 + m;
        unsigned ab = aAddr + buf * bufStride;
        unsigned bb = bAddr + buf * bufStride;
        if (valid) {
#pragma unroll
            for (int j = 0; j < 8; j++) {
                int kl = j * 2 + half;
                cp4(ab + kl * rowStride, ap + (c0 + kl) * HIN * HIN);
            }
        } else {
#pragma unroll
            for (int j = 0; j < 8; j++) {
                int kl = j * 2 + half;
                As[buf][kl][m] = 0.f;
            }
        }
#pragma unroll
        for (int j = 0; j < 8; j++) {
            int kl = j * 2 + half;
            cp4(bb + kl * rowStride, bp + kl * F);
        }
        cp_commit();
    };

    issue_tile(0, 0);

    for (int t = 0; t < NT; t++) {
        cp_wait0();
        __syncthreads();                 // tile t visible; compute t-1 done
        if (t + 1 < NT) issue_tile(t + 1, (t + 1) & 1);

        int cur = t & 1;
#pragma unroll
        for (int kk = 0; kk < 16; kk++) {
            const float4* a4 = reinterpret_cast<const float4*>(&As[cur][kk][trow * 8]);
            float4 a0 = a4[0];
            float4 a1 = a4[1];
            const ulonglong2* b2 = reinterpret_cast<const ulonglong2*>(&Bs[cur][kk][tcol * 8]);
            ulonglong2 b01 = b2[0];
            ulonglong2 b23 = b2[1];
            u64 bb4[4] = {b01.x, b01.y, b23.x, b23.y};
            u64 ad[8] = {dup2(a0.x), dup2(a0.y), dup2(a0.z), dup2(a0.w),
                         dup2(a1.x), dup2(a1.y), dup2(a1.z), dup2(a1.w)};
#pragma unroll
            for (int i = 0; i < 8; i++)
#pragma unroll
                for (int j = 0; j < 4; j++)
                    ffma2(acc[i][j], ad[i], bb4[j]);
        }
    }

    // epilogue
    int f0 = bn * 128 + tcol * 8;
#pragma unroll
    for (int i = 0; i < 8; i++) {
        int pix = bm * 128 + trow * 8 + i;
        float4 o0, o1;
        unpack2(acc[i][0], o0.x, o0.y);
        unpack2(acc[i][1], o0.z, o0.w);
        unpack2(acc[i][2], o1.x, o1.y);
        unpack2(acc[i][3], o1.z, o1.w);
        float* dst = &g_a[(size_t)pix * F + f0];
        *(float4*)dst = o0;
        *(float4*)(dst + 4) = o1;
    }
}

// ------------------------- exact top-k (with tie semantics) ----------------
__global__ void __launch_bounds__(256) topk_kernel() {
    int warp = blockIdx.x * 8 + (threadIdx.x >> 5);
    int lane = threadIdx.x & 31;
    if (warp >= NPIX) return;
    const float* ap = g_a + (size_t)warp * F;

    float v[16];
#pragma unroll
    for (int j = 0; j < 16; j++) v[j] = ap[j * 32 + lane];

    unsigned alive = 0xFFFFu;
    int removed = 0;
    float T = -3.4e38f;
    for (int it = 0; it < 16; it++) {
        float lm = -3.4e38f;
#pragma unroll
        for (int j = 0; j < 16; j++)
            if (alive & (1u << j)) lm = fmaxf(lm, v[j]);
#pragma unroll
        for (int o = 16; o > 0; o >>= 1)
            lm = fmaxf(lm, __shfl_xor_sync(0xffffffffu, lm, o));
        unsigned em = 0; int c = 0;
#pragma unroll
        for (int j = 0; j < 16; j++)
            if ((alive & (1u << j)) && v[j] == lm) { em |= 1u << j; c++; }
#pragma unroll
        for (int o = 16; o > 0; o >>= 1)
            c += __shfl_xor_sync(0xffffffffu, c, o);
        T = lm;
        if (removed + c >= 16) break;
        removed += c;
        alive &= ~em;
    }

    int base = 0;
#pragma unroll
    for (int j = 0; j < 16; j++) {
        bool keep = v[j] >= T;
        unsigned bal = __ballot_sync(0xffffffffu, keep);
        if (keep) {
            int pos = base + __popc(bal & ((1u << lane) - 1u));
            if (pos < 32) {
                g_spidx[warp * 32 + pos] = j * 32 + lane;
                g_spval[warp * 32 + pos] = v[j];
            }
        }
        base += __popc(bal);
    }
    if (lane == 0) g_spcnt[warp] = base < 32 ? base : 32;
}

// ------------------------- sparse adjoint recon + aux ----------------------
template<int CIN, int STRIDE, int HIN, bool L1>
__global__ void __launch_bounds__(256) recon_aux_kernel(const float* __restrict__ refp) {
    const int PPB = 256 / CIN;
    int tid = threadIdx.x;
    int c = tid % CIN;
    int pi = tid / CIN;
    int g = blockIdx.x * PPB + pi;
    int n = g / (HIN * HIN);
    int r = g - n * (HIN * HIN);
    int y = r / HIN, xx = r - y * HIN;
    const float* wrb = L1 ? g_wr1 : g_wr0;

    float recon = 0.f;
#pragma unroll
    for (int ky = 0; ky < 3; ky++) {
        int t = y + 1 - ky;
        int oy;
        if (STRIDE == 2) { if (t & 1) continue; oy = t >> 1; } else oy = t;
        if ((unsigned)oy >= 28u) continue;
#pragma unroll
        for (int kx = 0; kx < 3; kx++) {
            int s = xx + 1 - kx;
            int ox;
            if (STRIDE == 2) { if (s & 1) continue; ox = s >> 1; } else ox = s;
            if ((unsigned)ox >= 28u) continue;
            int q = (n * 28 + oy) * 28 + ox;
            int cnt = g_spcnt[q];
            const float* wb = wrb + (size_t)(ky * 3 + kx) * F * CIN;
            for (int e = 0; e < cnt; e++) {
                int fidx = g_spidx[q * 32 + e];
                float val = g_spval[q * 32 + e];
                recon += val * wb[fidx * CIN + c];
            }
        }
    }
    size_t ridx = ((size_t)(n * CIN + c) * HIN + y) * HIN + xx;
    float refv = L1 ? g_out0[ridx] : refp[ridx];
    float d = recon - refv;

    __shared__ float red[256];
    red[tid] = d * d;
    __syncthreads();
    for (int st = 128; st > 0; st >>= 1) {
        if (tid < st) red[tid] += red[tid + st];
        __syncthreads();
    }
    if (tid == 0) g_partial[blockIdx.x] = red[0];
}

__global__ void reduce_partials(int n, float scale, float* __restrict__ out) {
    __shared__ float red[256];
    float s = 0.f;
    for (int i = threadIdx.x; i < n; i += 256) s += g_partial[i];
    red[threadIdx.x] = s;
    __syncthreads();
    for (int st = 128; st > 0; st >>= 1) {
        if (threadIdx.x < st) red[threadIdx.x] += red[threadIdx.x + st];
        __syncthreads();
    }
    if (threadIdx.x == 0) *out = red[0] * scale;
}

// ------------------------- sparse 1x1 projection ---------------------------
__global__ void __launch_bounds__(256) proj_kernel(int slot) {
    float* out = (slot == 0) ? g_out0 : g_p1;
    const float* wp = (slot == 0) ? g_wpT0 : g_wpT1;
    int tid = threadIdx.x;
    int co = tid & 127;
    int pi = tid >> 7;
    int q = blockIdx.x * 2 + pi;
    int cnt = g_spcnt[q];
    float acc = 0.f;
    for (int e = 0; e < cnt; e++) {
        int f = g_spidx[q * 32 + e];
        acc += g_spval[q * 32 + e] * wp[f * COUT + co];
    }
    int n = q / 784, r = q - n * 784;
    out[(size_t)(n * COUT + co) * 784 + r] = acc;
}

// ------------------------- shortcut 1x1 stride-2 ---------------------------
__global__ void __launch_bounds__(256) shortcut_kernel(const float* __restrict__ x) {
    int tid = threadIdx.x;
    int co = tid & 127;
    int pi = tid >> 7;
    int q = blockIdx.x * 2 + pi;
    int n = q / 784, r = q - n * 784;
    int oy = r / 28, ox = r - oy * 28;
    const float* xp = x + (size_t)n * 64 * 3136 + (2 * oy) * 56 + 2 * ox;
    float acc = 0.f;
#pragma unroll
    for (int c = 0; c < 64; c++) acc = fmaf(xp[c * 3136], g_wscT[c * 128 + co], acc);
    g_psc[(size_t)(n * COUT + co) * 784 + r] = acc;
}

// ------------------------- batchnorm (training stats, double-precision) ----
__global__ void __launch_bounds__(256) bn_stats_kernel(int slot) {
    const float* src = (slot == 0) ? g_out0 : (slot == 1 ? g_p1 : g_psc);
    int co = blockIdx.x;
    int tid = threadIdx.x;
    double s = 0.0, s2 = 0.0;
    for (int n = 0; n < NIMG; n++) {
        const float* row = src + (size_t)(n * COUT + co) * 784;
        for (int r = tid; r < 784; r += 256) {
            double v = (double)row[r];
            s += v; s2 += v * v;
        }
    }
    __shared__ double rs[256], rq[256];
    rs[tid] = s; rq[tid] = s2;
    __syncthreads();
    for (int st = 128; st > 0; st >>= 1) {
        if (tid < st) { rs[tid] += rs[tid + st]; rq[tid] += rq[tid + st]; }
        __syncthreads();
    }
    if (tid == 0) {
        double mean = rs[0] * (1.0 / 50176.0);
        double var = rq[0] * (1.0 / 50176.0) - mean * mean;
        g_mean[slot][co] = (float)mean;
        g_rstd[slot][co] = rsqrtf((float)var + BN_EPS);
    }
}

// apply in reference op order: ((x-m)*r)*g + b
__global__ void __launch_bounds__(256) norm0_kernel(const float* __restrict__ gg,
                                                    const float* __restrict__ bb) {
    size_t i = (size_t)blockIdx.x * 256 + threadIdx.x;
    if (i >= OUTN) return;
    int co = (int)((i / 784) & 127);
    g_out0[i] = ((g_out0[i] - g_mean[0][co]) * g_rstd[0][co]) * gg[co] + bb[co];
}

__global__ void __launch_bounds__(256) final_kernel(float* __restrict__ dout,
        const float* __restrict__ g1, const float* __restrict__ b1,
        const float* __restrict__ gsc, const float* __restrict__ bsc) {
    size_t i = (size_t)blockIdx.x * 256 + threadIdx.x;
    if (i >= OUTN) return;
    int co = (int)((i / 784) & 127);
    float v1 = ((g_p1[i]  - g_mean[1][co]) * g_rstd[1][co]) * g1[co]  + b1[co];
    float v2 = ((g_psc[i] - g_mean[2][co]) * g_rstd[2][co]) * gsc[co] + bsc[co];
    float v = v1 + v2;
    dout[i] = v > 0.f ? v : 0.f;
}

// ---------------------------------------------------------------------------
extern "C" void kernel_launch(void* const* d_in, const int* in_sizes, int n_in,
                              void* d_out, int out_size) {
    const float* x       = (const float*)d_in[0];
    const float* w_enc0  = (const float*)d_in[1];
    const float* w_proj0 = (const float*)d_in[2];
    const float* g0      = (const float*)d_in[3];
    const float* b0      = (const float*)d_in[4];
    const float* w_enc1  = (const float*)d_in[5];
    const float* w_proj1 = (const float*)d_in[6];
    const float* g1      = (const float*)d_in[7];
    const float* b1      = (const float*)d_in[8];
    const float* w_sc    = (const float*)d_in[9];
    const float* g_sc    = (const float*)d_in[10];
    const float* b_sc    = (const float*)d_in[11];
    float* out = (float*)d_out;

    const int elem_blocks = (int)((OUTN + 255) / 256);

    // prep (3 launches so conv_enc L0 sits in the ncu -s 5 slot)
    transpose_wenc<<<(576 * 512 + 255) / 256, 256>>>(w_enc0, 64, 0);
    transpose_wenc<<<(1152 * 512 + 255) / 256, 256>>>(w_enc1, 128, 1);
    make_wr<<<(9 * 512 * 64 + 255) / 256, 256>>>(w_enc0, 64, 0);

    // ---------------- layer 0 ----------------
    conv_enc<64, 2, 56, false><<<dim3(NPIX / 128, 4), 256>>>(x);   // <- profiled
    topk_kernel<<<NPIX / 8, 256>>>();
    recon_aux_kernel<64, 2, 56, false><<<NIMG * 3136 / 4, 256>>>(x);
    reduce_partials<<<1, 256>>>(NIMG * 3136 / 4, 1.f / 12845056.f, out + out_size - 2);
    make_wpT<<<(512 * 128 + 255) / 256, 256>>>(w_proj0, 0);
    proj_kernel<<<NPIX / 2, 256>>>(0);
    bn_stats_kernel<<<128, 256>>>(0);
    norm0_kernel<<<elem_blocks, 256>>>(g0, b0);

    // ---------------- layer 1 ----------------
    conv_enc<128, 1, 28, true><<<dim3(NPIX / 128, 4), 256>>>(x);
    topk_kernel<<<NPIX / 8, 256>>>();
    make_wr<<<(9 * 512 * 128 + 255) / 256, 256>>>(w_enc1, 128, 1);
    recon_aux_kernel<128, 1, 28, true><<<NIMG * 784 / 2, 256>>>(nullptr);
    reduce_partials<<<1, 256>>>(NIMG * 784 / 2, 1.f / 6422528.f, out + out_size - 1);
    make_wpT<<<(512 * 128 + 255) / 256, 256>>>(w_proj1, 1);
    proj_kernel<<<NPIX / 2, 256>>>(1);
    bn_stats_kernel<<<128, 256>>>(1);

    // ---------------- shortcut + fuse ----------------
    make_wscT<<<(64 * 128 + 255) / 256, 256>>>(w_sc);
    shortcut_kernel<<<NPIX / 2, 256>>>(x);
    bn_stats_kernel<<<128, 256>>>(2);
    final_kernel<<<elem_blocks, 256>>>(out, g1, b1, g_sc, b_sc);
}

// round 5
// speedup vs baseline: 1.1100x; 1.0210x over previous
#include <cuda_runtime.h>
#include <cstdint>

// ---------------------------------------------------------------------------
// BasicBlock_Sparse: two sparse-coding layers + shortcut, fp32.
// NUMERICAL CONTRACT: encoder conv accumulation is a SINGLE sequential FMA
// chain per output, ascending k = (ky, kx, c) with c fastest (bit-matches
// XLA-CPU/Eigen im2col GEMM -> identical top-k selection). fma.rn.f32x2
// performs two independent IEEE fmas -> packing two filters per register
// preserves each chain bit-exactly.
// ---------------------------------------------------------------------------

#define NIMG 64
#define F    512
#define OHW  28
#define NPIX (NIMG*OHW*OHW)      // 50176
#define COUT 128
#define OUTN ((size_t)NPIX*COUT) // 6422528
#define BN_EPS 1e-5f

typedef unsigned long long u64;

// ------------------------- device scratch (static) -------------------------
__device__ float g_a[(size_t)NPIX*F];       // encoder activations [pix][F]
__device__ float g_spval[NPIX*32];
__device__ int   g_spidx[NPIX*32];
__device__ int   g_spcnt[NPIX];
__device__ float g_out0[OUTN];              // layer0 output (pre then normalized)
__device__ float g_p1[OUTN];                // layer1 proj pre-BN
__device__ float g_psc[OUTN];               // shortcut pre-BN
__device__ float g_wT0[576*512];            // enc0 weights [k=(ky,kx,c)][F]
__device__ float g_wT1[1152*512];           // enc1 weights [k][F]
__device__ float g_wr0[9*512*64];           // enc0 weights [kykx][F][C] for recon
__device__ float g_wr1[9*512*128];          // enc1 weights [kykx][F][C]
__device__ float g_wpT0[512*128];           // proj0 weights [F][COUT]
__device__ float g_wpT1[512*128];           // proj1 weights [F][COUT]
__device__ float g_wscT[64*128];            // shortcut weights [C][COUT]
__device__ float g_partial[NPIX];           // block partial sums (aux)
__device__ double2 g_bns[128*16];           // BN stage-1 partials
__device__ float g_mean[3][128];            // BN mean per slot {out0, p1, sc}
__device__ float g_rstd[3][128];            // BN rsqrt(var+eps) per slot

// ------------------------- asm helpers -------------------------------------
__device__ __forceinline__ void ffma2(u64& d, u64 a, u64 b) {
    asm("fma.rn.f32x2 %0, %1, %2, %0;" : "+l"(d) : "l"(a), "l"(b));
}
__device__ __forceinline__ u64 dup2(float x) {
    u64 r;
    unsigned xi = __float_as_uint(x);
    asm("mov.b64 %0, {%1, %1};" : "=l"(r) : "r"(xi));
    return r;
}
__device__ __forceinline__ void unpack2(u64 v, float& lo, float& hi) {
    unsigned a, b;
    asm("mov.b64 {%0, %1}, %2;" : "=r"(a), "=r"(b) : "l"(v));
    lo = __uint_as_float(a);
    hi = __uint_as_float(b);
}
__device__ __forceinline__ void cp4(unsigned dst, const float* src) {
    asm volatile("cp.async.ca.shared.global [%0], [%1], 4;" :: "r"(dst), "l"(src));
}
__device__ __forceinline__ void cp_commit() {
    asm volatile("cp.async.commit_group;");
}
__device__ __forceinline__ void cp_wait0() {
    asm volatile("cp.async.wait_group 0;");
}

// ------------------------- fused weight re-layout --------------------------
// Produces wT[k][f] (k=(ky,kx,c), c fastest) and wr[kykx][f][c].
// Both have 9*512*CIN elements -> single guard.
__global__ void prep_enc(const float* __restrict__ w, int CIN, int which) {
    float* wT = which ? g_wT1 : g_wT0;
    float* wr = which ? g_wr1 : g_wr0;
    int tot = 9 * 512 * CIN;
    int i = blockIdx.x * 256 + threadIdx.x;
    if (i >= tot) return;
    // wT: i = k*512+f, k = ky*3*CIN + kx*CIN + c
    {
        int k = i / 512, f = i - k * 512;
        int ky = k / (3 * CIN);
        int r  = k - ky * 3 * CIN;
        int kx = r / CIN;
        int c  = r - kx * CIN;
        wT[i] = w[(f * CIN + c) * 9 + ky * 3 + kx];
    }
    // wr: i = r9*512*CIN + f*CIN + c
    {
        int c = i % CIN;
        int f = (i / CIN) % 512;
        int r = i / (CIN * 512);
        wr[i] = w[(f * CIN + c) * 9 + r];
    }
}
__global__ void make_wpT(const float* __restrict__ wp, int which) {
    float* dst = which ? g_wpT1 : g_wpT0;
    int i = blockIdx.x * 256 + threadIdx.x;
    if (i >= 512 * 128) return;
    int f = i / 128, co = i - f * 128;
    dst[i] = wp[co * 512 + f];
}
__global__ void make_wscT(const float* __restrict__ w) {
    int i = blockIdx.x * 256 + threadIdx.x;
    if (i >= 64 * 128) return;
    int c = i / 128, co = i - c * 128;
    g_wscT[i] = w[co * 64 + c];
}

// ------------------------- encoder conv (implicit GEMM, f32x2) -------------
// Tile: BM=128 pixels x BN=128 filters x BK=16, 256 thr, microtile 8x8.
// cp.async double-buffered smem.
template<int CIN, int STRIDE, int HIN, bool L1>
__global__ void __launch_bounds__(256, 2) conv_enc(const float* __restrict__ xin) {
    const int K = CIN * 9;
    const int NT = K / 16;
    const float* __restrict__ src = L1 ? (const float*)g_out0 : xin;
    const float* __restrict__ wT = L1 ? g_wT1 : g_wT0;

    __shared__ float As[2][16][128];
    __shared__ float Bs[2][16][128];
    __shared__ int   sBase[128];
    __shared__ int   sOy[128];
    __shared__ int   sOx[128];

    int tid = threadIdx.x;
    int bm = blockIdx.x, bn = blockIdx.y;

    if (tid < 128) {
        int p = bm * 128 + tid;
        int n = p / 784;
        int r = p - n * 784;
        int oy = r / 28, ox = r - oy * 28;
        sOy[tid] = oy * STRIDE;
        sOx[tid] = ox * STRIDE;
        sBase[tid] = n * CIN * HIN * HIN + oy * STRIDE * HIN + ox * STRIDE;
    }
    __syncthreads();

    int m  = tid & 127;
    int half = tid >> 7;
    int base_m = sBase[m], oyS = sOy[m], oxS = sOx[m];

    unsigned aAddr = (unsigned)__cvta_generic_to_shared(&As[0][0][m]);
    unsigned bAddr = (unsigned)__cvta_generic_to_shared(&Bs[0][0][m]);
    const int bufStride = 16 * 128 * 4;
    const int rowStride = 128 * 4;

    int trow = tid >> 4;
    int tcol = tid & 15;

    u64 acc[8][4];
#pragma unroll
    for (int i = 0; i < 8; i++)
#pragma unroll
        for (int j = 0; j < 4; j++) acc[i][j] = 0ULL;

    auto issue_tile = [&](int t, int buf) {
        int kt = t * 16;
        int ky = kt / (3 * CIN);
        int rr = kt - ky * 3 * CIN;
        int kx = rr / CIN;
        int c0 = rr - kx * CIN;
        int iy = oyS + ky - 1, ix = oxS + kx - 1;
        bool valid = ((unsigned)iy < (unsigned)HIN) && ((unsigned)ix < (unsigned)HIN);
        const float* ap = src + base_m + (ky - 1) * HIN + (kx - 1);
        const float* bp = wT + (size_t)kt * F + bn * 128 + m;
        unsigned ab = aAddr + buf * bufStride;
        unsigned bb = bAddr + buf * bufStride;
        if (valid) {
#pragma unroll
            for (int j = 0; j < 8; j++) {
                int kl = j * 2 + half;
                cp4(ab + kl * rowStride, ap + (c0 + kl) * HIN * HIN);
            }
        } else {
#pragma unroll
            for (int j = 0; j < 8; j++) {
                int kl = j * 2 + half;
                As[buf][kl][m] = 0.f;
            }
        }
#pragma unroll
        for (int j = 0; j < 8; j++) {
            int kl = j * 2 + half;
            cp4(bb + kl * rowStride, bp + kl * F);
        }
        cp_commit();
    };

    issue_tile(0, 0);

    for (int t = 0; t < NT; t++) {
        cp_wait0();
        __syncthreads();
        if (t + 1 < NT) issue_tile(t + 1, (t + 1) & 1);

        int cur = t & 1;
#pragma unroll
        for (int kk = 0; kk < 16; kk++) {
            const float4* a4 = reinterpret_cast<const float4*>(&As[cur][kk][trow * 8]);
            float4 a0 = a4[0];
            float4 a1 = a4[1];
            const ulonglong2* b2 = reinterpret_cast<const ulonglong2*>(&Bs[cur][kk][tcol * 8]);
            ulonglong2 b01 = b2[0];
            ulonglong2 b23 = b2[1];
            u64 bb4[4] = {b01.x, b01.y, b23.x, b23.y};
            u64 ad[8] = {dup2(a0.x), dup2(a0.y), dup2(a0.z), dup2(a0.w),
                         dup2(a1.x), dup2(a1.y), dup2(a1.z), dup2(a1.w)};
#pragma unroll
            for (int i = 0; i < 8; i++)
#pragma unroll
                for (int j = 0; j < 4; j++)
                    ffma2(acc[i][j], ad[i], bb4[j]);
        }
    }

    int f0 = bn * 128 + tcol * 8;
#pragma unroll
    for (int i = 0; i < 8; i++) {
        int pix = bm * 128 + trow * 8 + i;
        float4 o0, o1;
        unpack2(acc[i][0], o0.x, o0.y);
        unpack2(acc[i][1], o0.z, o0.w);
        unpack2(acc[i][2], o1.x, o1.y);
        unpack2(acc[i][3], o1.z, o1.w);
        float* dst = &g_a[(size_t)pix * F + f0];
        *(float4*)dst = o0;
        *(float4*)(dst + 4) = o1;
    }
}

// ------------------------- exact top-k (with tie semantics) ----------------
__global__ void __launch_bounds__(256) topk_kernel() {
    int warp = blockIdx.x * 8 + (threadIdx.x >> 5);
    int lane = threadIdx.x & 31;
    if (warp >= NPIX) return;
    const float* ap = g_a + (size_t)warp * F;

    float v[16];
#pragma unroll
    for (int j = 0; j < 16; j++) v[j] = ap[j * 32 + lane];

    unsigned alive = 0xFFFFu;
    int removed = 0;
    float T = -3.4e38f;
    for (int it = 0; it < 16; it++) {
        float lm = -3.4e38f;
#pragma unroll
        for (int j = 0; j < 16; j++)
            if (alive & (1u << j)) lm = fmaxf(lm, v[j]);
#pragma unroll
        for (int o = 16; o > 0; o >>= 1)
            lm = fmaxf(lm, __shfl_xor_sync(0xffffffffu, lm, o));
        unsigned em = 0; int c = 0;
#pragma unroll
        for (int j = 0; j < 16; j++)
            if ((alive & (1u << j)) && v[j] == lm) { em |= 1u << j; c++; }
#pragma unroll
        for (int o = 16; o > 0; o >>= 1)
            c += __shfl_xor_sync(0xffffffffu, c, o);
        T = lm;
        if (removed + c >= 16) break;
        removed += c;
        alive &= ~em;
    }

    int base = 0;
#pragma unroll
    for (int j = 0; j < 16; j++) {
        bool keep = v[j] >= T;
        unsigned bal = __ballot_sync(0xffffffffu, keep);
        if (keep) {
            int pos = base + __popc(bal & ((1u << lane) - 1u));
            if (pos < 32) {
                g_spidx[warp * 32 + pos] = j * 32 + lane;
                g_spval[warp * 32 + pos] = v[j];
            }
        }
        base += __popc(bal);
    }
    if (lane == 0) g_spcnt[warp] = base < 32 ? base : 32;
}

// ------------------------- sparse adjoint recon + aux ----------------------
// Entry loop unrolled x4 with int4/float4 list loads -> 4 weight gathers in
// flight (MLP 4). Aux is continuous (1e-3 tol) so reassociation is free.
template<int CIN, int STRIDE, int HIN, bool L1>
__global__ void __launch_bounds__(256) recon_aux_kernel(const float* __restrict__ refp) {
    const int PPB = 256 / CIN;
    int tid = threadIdx.x;
    int c = tid % CIN;
    int pi = tid / CIN;
    int g = blockIdx.x * PPB + pi;
    int n = g / (HIN * HIN);
    int r = g - n * (HIN * HIN);
    int y = r / HIN, xx = r - y * HIN;
    const float* wrb = L1 ? g_wr1 : g_wr0;

    float recon = 0.f;
#pragma unroll
    for (int ky = 0; ky < 3; ky++) {
        int t = y + 1 - ky;
        int oy;
        if (STRIDE == 2) { if (t & 1) continue; oy = t >> 1; } else oy = t;
        if ((unsigned)oy >= 28u) continue;
#pragma unroll
        for (int kx = 0; kx < 3; kx++) {
            int s = xx + 1 - kx;
            int ox;
            if (STRIDE == 2) { if (s & 1) continue; ox = s >> 1; } else ox = s;
            if ((unsigned)ox >= 28u) continue;
            int q = (n * 28 + oy) * 28 + ox;
            int cnt = g_spcnt[q];
            const float* wb = wrb + (size_t)(ky * 3 + kx) * F * CIN + c;
            const int4*   ip = (const int4*)&g_spidx[q * 32];
            const float4* vp = (const float4*)&g_spval[q * 32];
            int nb = cnt >> 2;
            for (int b = 0; b < nb; b++) {
                int4   f4 = ip[b];
                float4 v4 = vp[b];
                float w0 = wb[f4.x * CIN];
                float w1 = wb[f4.y * CIN];
                float w2 = wb[f4.z * CIN];
                float w3 = wb[f4.w * CIN];
                recon += v4.x * w0;
                recon += v4.y * w1;
                recon += v4.z * w2;
                recon += v4.w * w3;
            }
            for (int e = nb * 4; e < cnt; e++)
                recon += g_spval[q * 32 + e] * wb[g_spidx[q * 32 + e] * CIN];
        }
    }
    size_t ridx = ((size_t)(n * CIN + c) * HIN + y) * HIN + xx;
    float refv = L1 ? g_out0[ridx] : refp[ridx];
    float d = recon - refv;

    __shared__ float red[256];
    red[tid] = d * d;
    __syncthreads();
    for (int st = 128; st > 0; st >>= 1) {
        if (tid < st) red[tid] += red[tid + st];
        __syncthreads();
    }
    if (tid == 0) g_partial[blockIdx.x] = red[0];
}

__global__ void reduce_partials(int n, float scale, float* __restrict__ out) {
    __shared__ float red[256];
    float s = 0.f;
    for (int i = threadIdx.x; i < n; i += 256) s += g_partial[i];
    red[threadIdx.x] = s;
    __syncthreads();
    for (int st = 128; st > 0; st >>= 1) {
        if (threadIdx.x < st) red[threadIdx.x] += red[threadIdx.x + st];
        __syncthreads();
    }
    if (threadIdx.x == 0) *out = red[0] * scale;
}

// ------------------------- sparse 1x1 projection (unrolled x4) -------------
__global__ void __launch_bounds__(256) proj_kernel(int slot) {
    float* out = (slot == 0) ? g_out0 : g_p1;
    const float* wp = (slot == 0) ? g_wpT0 : g_wpT1;
    int tid = threadIdx.x;
    int co = tid & 127;
    int pi = tid >> 7;
    int q = blockIdx.x * 2 + pi;
    int cnt = g_spcnt[q];
    const int4*   ip = (const int4*)&g_spidx[q * 32];
    const float4* vp = (const float4*)&g_spval[q * 32];
    float acc = 0.f;
    int nb = cnt >> 2;
    for (int b = 0; b < nb; b++) {
        int4   f4 = ip[b];
        float4 v4 = vp[b];
        float w0 = wp[f4.x * COUT + co];
        float w1 = wp[f4.y * COUT + co];
        float w2 = wp[f4.z * COUT + co];
        float w3 = wp[f4.w * COUT + co];
        acc += v4.x * w0;
        acc += v4.y * w1;
        acc += v4.z * w2;
        acc += v4.w * w3;
    }
    for (int e = nb * 4; e < cnt; e++)
        acc += g_spval[q * 32 + e] * wp[g_spidx[q * 32 + e] * COUT + co];
    int n = q / 784, r = q - n * 784;
    out[(size_t)(n * COUT + co) * 784 + r] = acc;
}

// ------------------------- shortcut 1x1 stride-2 ---------------------------
__global__ void __launch_bounds__(256) shortcut_kernel(const float* __restrict__ x) {
    int tid = threadIdx.x;
    int co = tid & 127;
    int pi = tid >> 7;
    int q = blockIdx.x * 2 + pi;
    int n = q / 784, r = q - n * 784;
    int oy = r / 28, ox = r - oy * 28;
    const float* xp = x + (size_t)n * 64 * 3136 + (2 * oy) * 56 + 2 * ox;
    float acc = 0.f;
#pragma unroll
    for (int c = 0; c < 64; c++) acc = fmaf(xp[c * 3136], g_wscT[c * 128 + co], acc);
    g_psc[(size_t)(n * COUT + co) * 784 + r] = acc;
}

// ------------------------- batchnorm stats (two-stage, double) -------------
__global__ void __launch_bounds__(256) bn_stage1(int slot) {
    const float* src = (slot == 0) ? g_out0 : (slot == 1 ? g_p1 : g_psc);
    int co = blockIdx.x;
    int chunk = blockIdx.y;          // 16 chunks of 4 images
    int tid = threadIdx.x;
    double s = 0.0, s2 = 0.0;
    for (int n = chunk * 4; n < chunk * 4 + 4; n++) {
        const float* row = src + (size_t)(n * COUT + co) * 784;
        for (int r = tid; r < 784; r += 256) {
            double v = (double)row[r];
            s += v; s2 += v * v;
        }
    }
    __shared__ double rs[256], rq[256];
    rs[tid] = s; rq[tid] = s2;
    __syncthreads();
    for (int st = 128; st > 0; st >>= 1) {
        if (tid < st) { rs[tid] += rs[tid + st]; rq[tid] += rq[tid + st]; }
        __syncthreads();
    }
    if (tid == 0) g_bns[co * 16 + chunk] = make_double2(rs[0], rq[0]);
}
__global__ void bn_stage2(int slot) {
    int co = threadIdx.x;            // 128 threads
    double s = 0.0, s2 = 0.0;
    for (int k = 0; k < 16; k++) {
        double2 p = g_bns[co * 16 + k];
        s += p.x; s2 += p.y;
    }
    double mean = s * (1.0 / 50176.0);
    double var = s2 * (1.0 / 50176.0) - mean * mean;
    g_mean[slot][co] = (float)mean;
    g_rstd[slot][co] = rsqrtf((float)var + BN_EPS);
}

// apply in reference op order: ((x-m)*r)*g + b
__global__ void __launch_bounds__(256) norm0_kernel(const float* __restrict__ gg,
                                                    const float* __restrict__ bb) {
    size_t i = (size_t)blockIdx.x * 256 + threadIdx.x;
    if (i >= OUTN) return;
    int co = (int)((i / 784) & 127);
    g_out0[i] = ((g_out0[i] - g_mean[0][co]) * g_rstd[0][co]) * gg[co] + bb[co];
}

__global__ void __launch_bounds__(256) final_kernel(float* __restrict__ dout,
        const float* __restrict__ g1, const float* __restrict__ b1,
        const float* __restrict__ gsc, const float* __restrict__ bsc) {
    size_t i = (size_t)blockIdx.x * 256 + threadIdx.x;
    if (i >= OUTN) return;
    int co = (int)((i / 784) & 127);
    float v1 = ((g_p1[i]  - g_mean[1][co]) * g_rstd[1][co]) * g1[co]  + b1[co];
    float v2 = ((g_psc[i] - g_mean[2][co]) * g_rstd[2][co]) * gsc[co] + bsc[co];
    float v = v1 + v2;
    dout[i] = v > 0.f ? v : 0.f;
}

// ---------------------------------------------------------------------------
extern "C" void kernel_launch(void* const* d_in, const int* in_sizes, int n_in,
                              void* d_out, int out_size) {
    const float* x       = (const float*)d_in[0];
    const float* w_enc0  = (const float*)d_in[1];
    const float* w_proj0 = (const float*)d_in[2];
    const float* g0      = (const float*)d_in[3];
    const float* b0      = (const float*)d_in[4];
    const float* w_enc1  = (const float*)d_in[5];
    const float* w_proj1 = (const float*)d_in[6];
    const float* g1      = (const float*)d_in[7];
    const float* b1      = (const float*)d_in[8];
    const float* w_sc    = (const float*)d_in[9];
    const float* g_sc    = (const float*)d_in[10];
    const float* b_sc    = (const float*)d_in[11];
    float* out = (float*)d_out;

    const int elem_blocks = (int)((OUTN + 255) / 256);
    dim3 bnGrid(128, 16);

    // ---------------- layer 0 ----------------
    prep_enc<<<(9 * 512 * 64 + 255) / 256, 256>>>(w_enc0, 64, 0);     // #1
    conv_enc<64, 2, 56, false><<<dim3(NPIX / 128, 4), 256>>>(x);      // #2
    topk_kernel<<<NPIX / 8, 256>>>();                                 // #3
    recon_aux_kernel<64, 2, 56, false><<<NIMG * 3136 / 4, 256>>>(x);  // #4 <- profiled
    reduce_partials<<<1, 256>>>(NIMG * 3136 / 4, 1.f / 12845056.f, out + out_size - 2);
    make_wpT<<<(512 * 128 + 255) / 256, 256>>>(w_proj0, 0);
    proj_kernel<<<NPIX / 2, 256>>>(0);
    bn_stage1<<<bnGrid, 256>>>(0);
    bn_stage2<<<1, 128>>>(0);
    norm0_kernel<<<elem_blocks, 256>>>(g0, b0);

    // ---------------- layer 1 ----------------
    prep_enc<<<(9 * 512 * 128 + 255) / 256, 256>>>(w_enc1, 128, 1);
    conv_enc<128, 1, 28, true><<<dim3(NPIX / 128, 4), 256>>>(x);
    topk_kernel<<<NPIX / 8, 256>>>();
    recon_aux_kernel<128, 1, 28, true><<<NIMG * 784 / 2, 256>>>(nullptr);
    reduce_partials<<<1, 256>>>(NIMG * 784 / 2, 1.f / 6422528.f, out + out_size - 1);
    make_wpT<<<(512 * 128 + 255) / 256, 256>>>(w_proj1, 1);
    proj_kernel<<<NPIX / 2, 256>>>(1);
    bn_stage1<<<bnGrid, 256>>>(1);
    bn_stage2<<<1, 128>>>(1);

    // ---------------- shortcut + fuse ----------------
    make_wscT<<<(64 * 128 + 255) / 256, 256>>>(w_sc);
    shortcut_kernel<<<NPIX / 2, 256>>>(x);
    bn_stage1<<<bnGrid, 256>>>(2);
    bn_stage2<<<1, 128>>>(2);
    final_kernel<<<elem_blocks, 256>>>(out, g1, b1, g_sc, b_sc);
}

// round 8
// speedup vs baseline: 1.2841x; 1.1569x over previous
#include <cuda_runtime.h>
#include <cstdint>

// ---------------------------------------------------------------------------
// BasicBlock_Sparse: two sparse-coding layers + shortcut, fp32.
// NUMERICAL CONTRACT: encoder conv accumulation is a SINGLE sequential FMA
// chain per output, ascending k = (ky, kx, c) with c fastest (bit-matches
// XLA-CPU/Eigen im2col GEMM -> identical top-k selection). fma.rn.f32x2
// performs two independent IEEE fmas -> packing two filters per register
// preserves each chain bit-exactly.
// ---------------------------------------------------------------------------

#define NIMG 64
#define F    512
#define OHW  28
#define NPIX (NIMG*OHW*OHW)      // 50176
#define COUT 128
#define OUTN ((size_t)NPIX*COUT) // 6422528
#define BN_EPS 1e-5f

typedef unsigned long long u64;

// ------------------------- device scratch (static) -------------------------
__device__ float g_a[(size_t)NPIX*F];       // encoder activations [pix][F]
__device__ float g_spval[NPIX*32];
__device__ int   g_spidx[NPIX*32];
__device__ int   g_spcnt[NPIX];
__device__ float g_out0[OUTN];              // layer0 output (pre then normalized)
__device__ float g_p1[OUTN];                // layer1 proj pre-BN
__device__ float g_psc[OUTN];               // shortcut pre-BN
__device__ float g_wT0[576*512];            // enc0 weights [k=(ky,kx,c)][F]
__device__ float g_wT1[1152*512];           // enc1 weights [k][F]
__device__ float g_wr0[9*512*64];           // enc0 weights [kykx][F][C] for recon
__device__ float g_wr1[9*512*128];          // enc1 weights [kykx][F][C]
__device__ float g_wpT0[512*128];           // proj0 weights [F][COUT]
__device__ float g_wpT1[512*128];           // proj1 weights [F][COUT]
__device__ float g_wscT[64*128];            // shortcut weights [C][COUT]
__device__ float g_partial[NPIX];           // block partial sums (aux)
__device__ double2 g_bns[128*16];           // BN stage-1 partials
__device__ float g_mean[3][128];            // BN mean per slot {out0, p1, sc}
__device__ float g_rstd[3][128];            // BN rsqrt(var+eps) per slot

// ------------------------- asm helpers -------------------------------------
__device__ __forceinline__ void ffma2(u64& d, u64 a, u64 b) {
    asm("fma.rn.f32x2 %0, %1, %2, %0;" : "+l"(d) : "l"(a), "l"(b));
}
__device__ __forceinline__ u64 dup2(float x) {
    u64 r;
    unsigned xi = __float_as_uint(x);
    asm("mov.b64 %0, {%1, %1};" : "=l"(r) : "r"(xi));
    return r;
}
__device__ __forceinline__ void unpack2(u64 v, float& lo, float& hi) {
    unsigned a, b;
    asm("mov.b64 {%0, %1}, %2;" : "=r"(a), "=r"(b) : "l"(v));
    lo = __uint_as_float(a);
    hi = __uint_as_float(b);
}
__device__ __forceinline__ void cp4(unsigned dst, const float* src) {
    asm volatile("cp.async.ca.shared.global [%0], [%1], 4;" :: "r"(dst), "l"(src));
}
__device__ __forceinline__ void cp_commit() {
    asm volatile("cp.async.commit_group;");
}
__device__ __forceinline__ void cp_wait0() {
    asm volatile("cp.async.wait_group 0;");
}

// ------------------------- fused weight re-layout --------------------------
__global__ void prep_enc(const float* __restrict__ w, int CIN, int which) {
    float* wT = which ? g_wT1 : g_wT0;
    float* wr = which ? g_wr1 : g_wr0;
    int tot = 9 * 512 * CIN;
    int i = blockIdx.x * 256 + threadIdx.x;
    if (i >= tot) return;
    {
        int k = i / 512, f = i - k * 512;
        int ky = k / (3 * CIN);
        int r  = k - ky * 3 * CIN;
        int kx = r / CIN;
        int c  = r - kx * CIN;
        wT[i] = w[(f * CIN + c) * 9 + ky * 3 + kx];
    }
    {
        int c = i % CIN;
        int f = (i / CIN) % 512;
        int r = i / (CIN * 512);
        wr[i] = w[(f * CIN + c) * 9 + r];
    }
}
__global__ void make_wpT(const float* __restrict__ wp, int which) {
    float* dst = which ? g_wpT1 : g_wpT0;
    int i = blockIdx.x * 256 + threadIdx.x;
    if (i >= 512 * 128) return;
    int f = i / 128, co = i - f * 128;
    dst[i] = wp[co * 512 + f];
}
__global__ void make_wscT(const float* __restrict__ w) {
    int i = blockIdx.x * 256 + threadIdx.x;
    if (i >= 64 * 128) return;
    int c = i / 128, co = i - c * 128;
    g_wscT[i] = w[co * 64 + c];
}

// ------------------------- encoder conv (implicit GEMM, f32x2) -------------
template<int CIN, int STRIDE, int HIN, bool L1>
__global__ void __launch_bounds__(256, 2) conv_enc(const float* __restrict__ xin) {
    const int K = CIN * 9;
    const int NT = K / 16;
    const float* __restrict__ src = L1 ? (const float*)g_out0 : xin;
    const float* __restrict__ wT = L1 ? g_wT1 : g_wT0;

    __shared__ float As[2][16][128];
    __shared__ float Bs[2][16][128];
    __shared__ int   sBase[128];
    __shared__ int   sOy[128];
    __shared__ int   sOx[128];

    int tid = threadIdx.x;
    int bm = blockIdx.x, bn = blockIdx.y;

    if (tid < 128) {
        int p = bm * 128 + tid;
        int n = p / 784;
        int r = p - n * 784;
        int oy = r / 28, ox = r - oy * 28;
        sOy[tid] = oy * STRIDE;
        sOx[tid] = ox * STRIDE;
        sBase[tid] = n * CIN * HIN * HIN + oy * STRIDE * HIN + ox * STRIDE;
    }
    __syncthreads();

    int m  = tid & 127;
    int half = tid >> 7;
    int base_m = sBase[m], oyS = sOy[m], oxS = sOx[m];

    unsigned aAddr = (unsigned)__cvta_generic_to_shared(&As[0][0][m]);
    unsigned bAddr = (unsigned)__cvta_generic_to_shared(&Bs[0][0][m]);
    const int bufStride = 16 * 128 * 4;
    const int rowStride = 128 * 4;

    int trow = tid >> 4;
    int tcol = tid & 15;

    u64 acc[8][4];
#pragma unroll
    for (int i = 0; i < 8; i++)
#pragma unroll
        for (int j = 0; j < 4; j++) acc[i][j] = 0ULL;

    auto issue_tile = [&](int t, int buf) {
        int kt = t * 16;
        int ky = kt / (3 * CIN);
        int rr = kt - ky * 3 * CIN;
        int kx = rr / CIN;
        int c0 = rr - kx * CIN;
        int iy = oyS + ky - 1, ix = oxS + kx - 1;
        bool valid = ((unsigned)iy < (unsigned)HIN) && ((unsigned)ix < (unsigned)HIN);
        const float* ap = src + base_m + (ky - 1) * HIN + (kx - 1);
        const float* bp = wT + (size_t)kt * F + bn * 128 + m;
        unsigned ab = aAddr + buf * bufStride;
        unsigned bb = bAddr + buf * bufStride;
        if (valid) {
#pragma unroll
            for (int j = 0; j < 8; j++) {
                int kl = j * 2 + half;
                cp4(ab + kl * rowStride, ap + (c0 + kl) * HIN * HIN);
            }
        } else {
#pragma unroll
            for (int j = 0; j < 8; j++) {
                int kl = j * 2 + half;
                As[buf][kl][m] = 0.f;
            }
        }
#pragma unroll
        for (int j = 0; j < 8; j++) {
            int kl = j * 2 + half;
            cp4(bb + kl * rowStride, bp + kl * F);
        }
        cp_commit();
    };

    issue_tile(0, 0);

    for (int t = 0; t < NT; t++) {
        cp_wait0();
        __syncthreads();
        if (t + 1 < NT) issue_tile(t + 1, (t + 1) & 1);

        int cur = t & 1;
#pragma unroll
        for (int kk = 0; kk < 16; kk++) {
            const float4* a4 = reinterpret_cast<const float4*>(&As[cur][kk][trow * 8]);
            float4 a0 = a4[0];
            float4 a1 = a4[1];
            const ulonglong2* b2 = reinterpret_cast<const ulonglong2*>(&Bs[cur][kk][tcol * 8]);
            ulonglong2 b01 = b2[0];
            ulonglong2 b23 = b2[1];
            u64 bb4[4] = {b01.x, b01.y, b23.x, b23.y};
            u64 ad[8] = {dup2(a0.x), dup2(a0.y), dup2(a0.z), dup2(a0.w),
                         dup2(a1.x), dup2(a1.y), dup2(a1.z), dup2(a1.w)};
#pragma unroll
            for (int i = 0; i < 8; i++)
#pragma unroll
                for (int j = 0; j < 4; j++)
                    ffma2(acc[i][j], ad[i], bb4[j]);
        }
    }

    int f0 = bn * 128 + tcol * 8;
#pragma unroll
    for (int i = 0; i < 8; i++) {
        int pix = bm * 128 + trow * 8 + i;
        float4 o0, o1;
        unpack2(acc[i][0], o0.x, o0.y);
        unpack2(acc[i][1], o0.z, o0.w);
        unpack2(acc[i][2], o1.x, o1.y);
        unpack2(acc[i][3], o1.z, o1.w);
        float* dst = &g_a[(size_t)pix * F + f0];
        *(float4*)dst = o0;
        *(float4*)(dst + 4) = o1;
    }
}

// ------------------------- exact top-k (with tie semantics) ----------------
__global__ void __launch_bounds__(256) topk_kernel() {
    int warp = blockIdx.x * 8 + (threadIdx.x >> 5);
    int lane = threadIdx.x & 31;
    if (warp >= NPIX) return;
    const float* ap = g_a + (size_t)warp * F;

    float v[16];
#pragma unroll
    for (int j = 0; j < 16; j++) v[j] = ap[j * 32 + lane];

    unsigned alive = 0xFFFFu;
    int removed = 0;
    float T = -3.4e38f;
    for (int it = 0; it < 16; it++) {
        float lm = -3.4e38f;
#pragma unroll
        for (int j = 0; j < 16; j++)
            if (alive & (1u << j)) lm = fmaxf(lm, v[j]);
#pragma unroll
        for (int o = 16; o > 0; o >>= 1)
            lm = fmaxf(lm, __shfl_xor_sync(0xffffffffu, lm, o));
        unsigned em = 0; int c = 0;
#pragma unroll
        for (int j = 0; j < 16; j++)
            if ((alive & (1u << j)) && v[j] == lm) { em |= 1u << j; c++; }
#pragma unroll
        for (int o = 16; o > 0; o >>= 1)
            c += __shfl_xor_sync(0xffffffffu, c, o);
        T = lm;
        if (removed + c >= 16) break;
        removed += c;
        alive &= ~em;
    }

    int base = 0;
#pragma unroll
    for (int j = 0; j < 16; j++) {
        bool keep = v[j] >= T;
        unsigned bal = __ballot_sync(0xffffffffu, keep);
        if (keep) {
            int pos = base + __popc(bal & ((1u << lane) - 1u));
            if (pos < 32) {
                g_spidx[warp * 32 + pos] = j * 32 + lane;
                g_spval[warp * 32 + pos] = v[j];
            }
        }
        base += __popc(bal);
    }
    if (lane == 0) g_spcnt[warp] = base < 32 ? base : 32;
}

// ------------------------- sparse adjoint recon + aux (float4/channel) -----
// Each thread owns 4 channels of one input pixel: one LDG.128 weight gather
// feeds 4 FMAs -> address arithmetic amortized 4x (R5 profile: alu-bound).
template<int CIN, int STRIDE, int HIN, bool L1>
__global__ void __launch_bounds__(256) recon_aux_kernel(const float* __restrict__ refp) {
    const int TPP = CIN / 4;            // threads per pixel
    const int PPB = 256 / TPP;          // pixels per block
    int tid = threadIdx.x;
    int cg = tid % TPP;
    int c0 = cg * 4;
    int pi = tid / TPP;
    int g = blockIdx.x * PPB + pi;
    int n = g / (HIN * HIN);
    int r = g - n * (HIN * HIN);
    int y = r / HIN, xx = r - y * HIN;
    const float* wrb = L1 ? g_wr1 : g_wr0;

    float4 recon = {0.f, 0.f, 0.f, 0.f};
#pragma unroll
    for (int ky = 0; ky < 3; ky++) {
        int t = y + 1 - ky;
        int oy;
        if (STRIDE == 2) { if (t & 1) continue; oy = t >> 1; } else oy = t;
        if ((unsigned)oy >= 28u) continue;
#pragma unroll
        for (int kx = 0; kx < 3; kx++) {
            int s = xx + 1 - kx;
            int ox;
            if (STRIDE == 2) { if (s & 1) continue; ox = s >> 1; } else ox = s;
            if ((unsigned)ox >= 28u) continue;
            int q = (n * 28 + oy) * 28 + ox;
            int cnt = g_spcnt[q];
            const float* wb = wrb + (size_t)(ky * 3 + kx) * F * CIN + c0;
            const int4*   ip = (const int4*)&g_spidx[q * 32];
            const float4* vp = (const float4*)&g_spval[q * 32];
            int nb = cnt >> 2;
            for (int b = 0; b < nb; b++) {
                int4   f4 = ip[b];
                float4 v4 = vp[b];
                float4 w0 = *(const float4*)&wb[f4.x * CIN];
                float4 w1 = *(const float4*)&wb[f4.y * CIN];
                float4 w2 = *(const float4*)&wb[f4.z * CIN];
                float4 w3 = *(const float4*)&wb[f4.w * CIN];
                recon.x += v4.x * w0.x; recon.y += v4.x * w0.y;
                recon.z += v4.x * w0.z; recon.w += v4.x * w0.w;
                recon.x += v4.y * w1.x; recon.y += v4.y * w1.y;
                recon.z += v4.y * w1.z; recon.w += v4.y * w1.w;
                recon.x += v4.z * w2.x; recon.y += v4.z * w2.y;
                recon.z += v4.z * w2.z; recon.w += v4.z * w2.w;
                recon.x += v4.w * w3.x; recon.y += v4.w * w3.y;
                recon.z += v4.w * w3.z; recon.w += v4.w * w3.w;
            }
            for (int e = nb * 4; e < cnt; e++) {
                float vv = g_spval[q * 32 + e];
                const float4 ww = *(const float4*)&wb[g_spidx[q * 32 + e] * CIN];
                recon.x += vv * ww.x; recon.y += vv * ww.y;
                recon.z += vv * ww.z; recon.w += vv * ww.w;
            }
        }
    }
    const float* refbase = L1 ? (const float*)g_out0 : refp;
    size_t ridx = ((size_t)(n * CIN + c0) * HIN + y) * HIN + xx;
    const size_t cs = (size_t)HIN * HIN;
    float d0 = recon.x - refbase[ridx];
    float d1 = recon.y - refbase[ridx + cs];
    float d2 = recon.z - refbase[ridx + 2 * cs];
    float d3 = recon.w - refbase[ridx + 3 * cs];
    float dd = d0 * d0 + d1 * d1 + d2 * d2 + d3 * d3;

    __shared__ float red[256];
    red[tid] = dd;
    __syncthreads();
    for (int st = 128; st > 0; st >>= 1) {
        if (tid < st) red[tid] += red[tid + st];
        __syncthreads();
    }
    if (tid == 0) g_partial[blockIdx.x] = red[0];
}

__global__ void reduce_partials(int n, float scale, float* __restrict__ out) {
    __shared__ float red[256];
    float s = 0.f;
    for (int i = threadIdx.x; i < n; i += 256) s += g_partial[i];
    red[threadIdx.x] = s;
    __syncthreads();
    for (int st = 128; st > 0; st >>= 1) {
        if (threadIdx.x < st) red[threadIdx.x] += red[threadIdx.x + st];
        __syncthreads();
    }
    if (threadIdx.x == 0) *out = red[0] * scale;
}

// ------------------------- sparse 1x1 projection (unrolled x4) -------------
__global__ void __launch_bounds__(256) proj_kernel(int slot) {
    float* out = (slot == 0) ? g_out0 : g_p1;
    const float* wp = (slot == 0) ? g_wpT0 : g_wpT1;
    int tid = threadIdx.x;
    int co = tid & 127;
    int pi = tid >> 7;
    int q = blockIdx.x * 2 + pi;
    int cnt = g_spcnt[q];
    const int4*   ip = (const int4*)&g_spidx[q * 32];
    const float4* vp = (const float4*)&g_spval[q * 32];
    float acc = 0.f;
    int nb = cnt >> 2;
    for (int b = 0; b < nb; b++) {
        int4   f4 = ip[b];
        float4 v4 = vp[b];
        float w0 = wp[f4.x * COUT + co];
        float w1 = wp[f4.y * COUT + co];
        float w2 = wp[f4.z * COUT + co];
        float w3 = wp[f4.w * COUT + co];
        acc += v4.x * w0;
        acc += v4.y * w1;
        acc += v4.z * w2;
        acc += v4.w * w3;
    }
    for (int e = nb * 4; e < cnt; e++)
        acc += g_spval[q * 32 + e] * wp[g_spidx[q * 32 + e] * COUT + co];
    int n = q / 784, r = q - n * 784;
    out[(size_t)(n * COUT + co) * 784 + r] = acc;
}

// ------------------------- shortcut 1x1 stride-2 ---------------------------
__global__ void __launch_bounds__(256) shortcut_kernel(const float* __restrict__ x) {
    int tid = threadIdx.x;
    int co = tid & 127;
    int pi = tid >> 7;
    int q = blockIdx.x * 2 + pi;
    int n = q / 784, r = q - n * 784;
    int oy = r / 28, ox = r - oy * 28;
    const float* xp = x + (size_t)n * 64 * 3136 + (2 * oy) * 56 + 2 * ox;
    float acc = 0.f;
#pragma unroll
    for (int c = 0; c < 64; c++) acc = fmaf(xp[c * 3136], g_wscT[c * 128 + co], acc);
    g_psc[(size_t)(n * COUT + co) * 784 + r] = acc;
}

// ------------------------- batchnorm stats (two-stage, double) -------------
__global__ void __launch_bounds__(256) bn_stage1(int slot) {
    const float* src = (slot == 0) ? g_out0 : (slot == 1 ? g_p1 : g_psc);
    int co = blockIdx.x;
    int chunk = blockIdx.y;
    int tid = threadIdx.x;
    double s = 0.0, s2 = 0.0;
    for (int n = chunk * 4; n < chunk * 4 + 4; n++) {
        const float* row = src + (size_t)(n * COUT + co) * 784;
        for (int r = tid; r < 784; r += 256) {
            double v = (double)row[r];
            s += v; s2 += v * v;
        }
    }
    __shared__ double rs[256], rq[256];
    rs[tid] = s; rq[tid] = s2;
    __syncthreads();
    for (int st = 128; st > 0; st >>= 1) {
        if (tid < st) { rs[tid] += rs[tid + st]; rq[tid] += rq[tid + st]; }
        __syncthreads();
    }
    if (tid == 0) g_bns[co * 16 + chunk] = make_double2(rs[0], rq[0]);
}
__global__ void bn_stage2(int slot) {
    int co = threadIdx.x;
    double s = 0.0, s2 = 0.0;
    for (int k = 0; k < 16; k++) {
        double2 p = g_bns[co * 16 + k];
        s += p.x; s2 += p.y;
    }
    double mean = s * (1.0 / 50176.0);
    double var = s2 * (1.0 / 50176.0) - mean * mean;
    g_mean[slot][co] = (float)mean;
    g_rstd[slot][co] = rsqrtf((float)var + BN_EPS);
}

__global__ void __launch_bounds__(256) norm0_kernel(const float* __restrict__ gg,
                                                    const float* __restrict__ bb) {
    size_t i = (size_t)blockIdx.x * 256 + threadIdx.x;
    if (i >= OUTN) return;
    int co = (int)((i / 784) & 127);
    g_out0[i] = ((g_out0[i] - g_mean[0][co]) * g_rstd[0][co]) * gg[co] + bb[co];
}

__global__ void __launch_bounds__(256) final_kernel(float* __restrict__ dout,
        const float* __restrict__ g1, const float* __restrict__ b1,
        const float* __restrict__ gsc, const float* __restrict__ bsc) {
    size_t i = (size_t)blockIdx.x * 256 + threadIdx.x;
    if (i >= OUTN) return;
    int co = (int)((i / 784) & 127);
    float v1 = ((g_p1[i]  - g_mean[1][co]) * g_rstd[1][co]) * g1[co]  + b1[co];
    float v2 = ((g_psc[i] - g_mean[2][co]) * g_rstd[2][co]) * gsc[co] + bsc[co];
    float v = v1 + v2;
    dout[i] = v > 0.f ? v : 0.f;
}

// ---------------------------------------------------------------------------
extern "C" void kernel_launch(void* const* d_in, const int* in_sizes, int n_in,
                              void* d_out, int out_size) {
    const float* x       = (const float*)d_in[0];
    const float* w_enc0  = (const float*)d_in[1];
    const float* w_proj0 = (const float*)d_in[2];
    const float* g0      = (const float*)d_in[3];
    const float* b0      = (const float*)d_in[4];
    const float* w_enc1  = (const float*)d_in[5];
    const float* w_proj1 = (const float*)d_in[6];
    const float* g1      = (const float*)d_in[7];
    const float* b1      = (const float*)d_in[8];
    const float* w_sc    = (const float*)d_in[9];
    const float* g_sc    = (const float*)d_in[10];
    const float* b_sc    = (const float*)d_in[11];
    float* out = (float*)d_out;

    const int elem_blocks = (int)((OUTN + 255) / 256);
    dim3 bnGrid(128, 16);

    // ---------------- layer 0 ----------------
    prep_enc<<<(9 * 512 * 64 + 255) / 256, 256>>>(w_enc0, 64, 0);     // #1
    make_wpT<<<(512 * 128 + 255) / 256, 256>>>(w_proj0, 0);           // #2
    conv_enc<64, 2, 56, false><<<dim3(NPIX / 128, 4), 256>>>(x);      // #3
    topk_kernel<<<NPIX / 8, 256>>>();                                 // #4 <- profiled
    recon_aux_kernel<64, 2, 56, false><<<NIMG * 3136 / 16, 256>>>(x);
    reduce_partials<<<1, 256>>>(NIMG * 3136 / 16, 1.f / 12845056.f, out + out_size - 2);
    proj_kernel<<<NPIX / 2, 256>>>(0);
    bn_stage1<<<bnGrid, 256>>>(0);
    bn_stage2<<<1, 128>>>(0);
    norm0_kernel<<<elem_blocks, 256>>>(g0, b0);

    // ---------------- layer 1 ----------------
    prep_enc<<<(9 * 512 * 128 + 255) / 256, 256>>>(w_enc1, 128, 1);
    conv_enc<128, 1, 28, true><<<dim3(NPIX / 128, 4), 256>>>(x);
    topk_kernel<<<NPIX / 8, 256>>>();
    recon_aux_kernel<128, 1, 28, true><<<NIMG * 784 / 8, 256>>>(nullptr);
    reduce_partials<<<1, 256>>>(NIMG * 784 / 8, 1.f / 6422528.f, out + out_size - 1);
    make_wpT<<<(512 * 128 + 255) / 256, 256>>>(w_proj1, 1);
    proj_kernel<<<NPIX / 2, 256>>>(1);
    bn_stage1<<<bnGrid, 256>>>(1);
    bn_stage2<<<1, 128>>>(1);

    // ---------------- shortcut + fuse ----------------
    make_wscT<<<(64 * 128 + 255) / 256, 256>>>(w_sc);
    shortcut_kernel<<<NPIX / 2, 256>>>(x);
    bn_stage1<<<bnGrid, 256>>>(2);
    bn_stage2<<<1, 128>>>(2);
    final_kernel<<<elem_blocks, 256>>>(out, g1, b1, g_sc, b_sc);
}

// round 9
// speedup vs baseline: 1.4978x; 1.1664x over previous
#include <cuda_runtime.h>
#include <cstdint>

// ---------------------------------------------------------------------------
// BasicBlock_Sparse: two sparse-coding layers + shortcut, fp32.
// NUMERICAL CONTRACT: encoder conv accumulation is a SINGLE sequential FMA
// chain per output, ascending k = (ky, kx, c) with c fastest (bit-matches
// XLA-CPU/Eigen im2col GEMM -> identical top-k selection). fma.rn.f32x2
// performs two independent IEEE fmas -> packing two filters per register
// preserves each chain bit-exactly.
// ---------------------------------------------------------------------------

#define NIMG 64
#define F    512
#define OHW  28
#define NPIX (NIMG*OHW*OHW)      // 50176
#define COUT 128
#define OUTN ((size_t)NPIX*COUT) // 6422528
#define BN_EPS 1e-5f

typedef unsigned long long u64;

// ------------------------- device scratch (static) -------------------------
__device__ float g_a[(size_t)NPIX*F];       // encoder activations [pix][F]
__device__ float g_spval[NPIX*32];
__device__ int   g_spidx[NPIX*32];
__device__ int   g_spcnt[NPIX];
__device__ float g_out0[OUTN];              // layer0 output (pre then normalized)
__device__ float g_p1[OUTN];                // layer1 proj pre-BN
__device__ float g_psc[OUTN];               // shortcut pre-BN
__device__ float g_wT0[576*512];            // enc0 weights [k=(ky,kx,c)][F]
__device__ float g_wT1[1152*512];           // enc1 weights [k][F]
__device__ float g_wr0[9*512*64];           // enc0 weights [kykx][F][C] for recon
__device__ float g_wr1[9*512*128];          // enc1 weights [kykx][F][C]
__device__ float g_wpT0[512*128];           // proj0 weights [F][COUT]
__device__ float g_wpT1[512*128];           // proj1 weights [F][COUT]
__device__ float g_wscT[64*128];            // shortcut weights [C][COUT]
__device__ float g_partial[NPIX];           // block partial sums (aux)
__device__ double2 g_bns[128*16];           // BN stage-1 partials
__device__ float g_mean[3][128];            // BN mean per slot {out0, p1, sc}
__device__ float g_rstd[3][128];            // BN rsqrt(var+eps) per slot

// ------------------------- asm helpers -------------------------------------
__device__ __forceinline__ void ffma2(u64& d, u64 a, u64 b) {
    asm("fma.rn.f32x2 %0, %1, %2, %0;" : "+l"(d) : "l"(a), "l"(b));
}
__device__ __forceinline__ u64 dup2(float x) {
    u64 r;
    unsigned xi = __float_as_uint(x);
    asm("mov.b64 %0, {%1, %1};" : "=l"(r) : "r"(xi));
    return r;
}
__device__ __forceinline__ void unpack2(u64 v, float& lo, float& hi) {
    unsigned a, b;
    asm("mov.b64 {%0, %1}, %2;" : "=r"(a), "=r"(b) : "l"(v));
    lo = __uint_as_float(a);
    hi = __uint_as_float(b);
}
__device__ __forceinline__ void cp4(unsigned dst, const float* src) {
    asm volatile("cp.async.ca.shared.global [%0], [%1], 4;" :: "r"(dst), "l"(src));
}
__device__ __forceinline__ void cp_commit() {
    asm volatile("cp.async.commit_group;");
}
__device__ __forceinline__ void cp_wait0() {
    asm volatile("cp.async.wait_group 0;");
}
// monotonic float->uint transform (order-preserving, strictly)
__device__ __forceinline__ unsigned fkey(float f) {
    unsigned b = __float_as_uint(f);
    return b ^ (unsigned)(((int)b >> 31) | 0x80000000);
}

// ------------------------- fused weight re-layout --------------------------
__global__ void prep_enc(const float* __restrict__ w, int CIN, int which) {
    float* wT = which ? g_wT1 : g_wT0;
    float* wr = which ? g_wr1 : g_wr0;
    int tot = 9 * 512 * CIN;
    int i = blockIdx.x * 256 + threadIdx.x;
    if (i >= tot) return;
    {
        int k = i / 512, f = i - k * 512;
        int ky = k / (3 * CIN);
        int r  = k - ky * 3 * CIN;
        int kx = r / CIN;
        int c  = r - kx * CIN;
        wT[i] = w[(f * CIN + c) * 9 + ky * 3 + kx];
    }
    {
        int c = i % CIN;
        int f = (i / CIN) % 512;
        int r = i / (CIN * 512);
        wr[i] = w[(f * CIN + c) * 9 + r];
    }
}
__global__ void make_wpT(const float* __restrict__ wp, int which) {
    float* dst = which ? g_wpT1 : g_wpT0;
    int i = blockIdx.x * 256 + threadIdx.x;
    if (i >= 512 * 128) return;
    int f = i / 128, co = i - f * 128;
    dst[i] = wp[co * 512 + f];
}
__global__ void make_wscT(const float* __restrict__ w) {
    int i = blockIdx.x * 256 + threadIdx.x;
    if (i >= 64 * 128) return;
    int c = i / 128, co = i - c * 128;
    g_wscT[i] = w[co * 64 + c];
}

// ------------------------- encoder conv (implicit GEMM, f32x2) -------------
// Tile: BM=128 pixels x BN=128 filters x BK=16, 128 threads, microtile 16x8.
// smem traffic 0.75 B/MAC (vs 1.0 at 8x8) -- R4 profile showed L1-bound.
template<int CIN, int STRIDE, int HIN, bool L1>
__global__ void __launch_bounds__(128, 2) conv_enc(const float* __restrict__ xin) {
    const int K = CIN * 9;
    const int NT = K / 16;
    const float* __restrict__ src = L1 ? (const float*)g_out0 : xin;
    const float* __restrict__ wT = L1 ? g_wT1 : g_wT0;

    __shared__ float As[2][16][128];
    __shared__ float Bs[2][16][128];
    __shared__ int   sBase[128];
    __shared__ int   sOy[128];
    __shared__ int   sOx[128];

    int tid = threadIdx.x;       // 0..127
    int bm = blockIdx.x, bn = blockIdx.y;

    {
        int p = bm * 128 + tid;
        int n = p / 784;
        int r = p - n * 784;
        int oy = r / 28, ox = r - oy * 28;
        sOy[tid] = oy * STRIDE;
        sOx[tid] = ox * STRIDE;
        sBase[tid] = n * CIN * HIN * HIN + oy * STRIDE * HIN + ox * STRIDE;
    }
    __syncthreads();

    int m = tid;                 // loader column (pixel for A, filter for B)
    int base_m = sBase[m], oyS = sOy[m], oxS = sOx[m];

    unsigned aAddr = (unsigned)__cvta_generic_to_shared(&As[0][0][m]);
    unsigned bAddr = (unsigned)__cvta_generic_to_shared(&Bs[0][0][m]);
    const int bufStride = 16 * 128 * 4;
    const int rowStride = 128 * 4;

    int trow = tid >> 4;         // 0..7  -> 16 pixels
    int tcol = tid & 15;         // 0..15 -> 8 filters (4 f32x2 pairs)

    u64 acc[16][4];
#pragma unroll
    for (int i = 0; i < 16; i++)
#pragma unroll
        for (int j = 0; j < 4; j++) acc[i][j] = 0ULL;

    auto issue_tile = [&](int t, int buf) {
        int kt = t * 16;
        int ky = kt / (3 * CIN);
        int rr = kt - ky * 3 * CIN;
        int kx = rr / CIN;
        int c0 = rr - kx * CIN;
        int iy = oyS + ky - 1, ix = oxS + kx - 1;
        bool valid = ((unsigned)iy < (unsigned)HIN) && ((unsigned)ix < (unsigned)HIN);
        const float* ap = src + base_m + (ky - 1) * HIN + (kx - 1);
        const float* bp = wT + (size_t)kt * F + bn * 128 + m;
        unsigned ab = aAddr + buf * bufStride;
        unsigned bb = bAddr + buf * bufStride;
        if (valid) {
#pragma unroll
            for (int kl = 0; kl < 16; kl++)
                cp4(ab + kl * rowStride, ap + (c0 + kl) * HIN * HIN);
        } else {
#pragma unroll
            for (int kl = 0; kl < 16; kl++)
                As[buf][kl][m] = 0.f;
        }
#pragma unroll
        for (int kl = 0; kl < 16; kl++)
            cp4(bb + kl * rowStride, bp + kl * F);
        cp_commit();
    };

    issue_tile(0, 0);

    for (int t = 0; t < NT; t++) {
        cp_wait0();
        __syncthreads();             // tile t visible; compute t-1 done
        if (t + 1 < NT) issue_tile(t + 1, (t + 1) & 1);

        int cur = t & 1;
#pragma unroll
        for (int kk = 0; kk < 16; kk++) {
            const float4* a4 = reinterpret_cast<const float4*>(&As[cur][kk][trow * 16]);
            float4 a0 = a4[0], a1 = a4[1], a2 = a4[2], a3 = a4[3];
            const ulonglong2* b2 = reinterpret_cast<const ulonglong2*>(&Bs[cur][kk][tcol * 8]);
            ulonglong2 b01 = b2[0];
            ulonglong2 b23 = b2[1];
            u64 bb4[4] = {b01.x, b01.y, b23.x, b23.y};
            float av[16] = {a0.x, a0.y, a0.z, a0.w, a1.x, a1.y, a1.z, a1.w,
                            a2.x, a2.y, a2.z, a2.w, a3.x, a3.y, a3.z, a3.w};
#pragma unroll
            for (int i = 0; i < 16; i++) {
                u64 ai = dup2(av[i]);
#pragma unroll
                for (int j = 0; j < 4; j++)
                    ffma2(acc[i][j], ai, bb4[j]);
            }
        }
    }

    int f0 = bn * 128 + tcol * 8;
#pragma unroll
    for (int i = 0; i < 16; i++) {
        int pix = bm * 128 + trow * 16 + i;
        float4 o0, o1;
        unpack2(acc[i][0], o0.x, o0.y);
        unpack2(acc[i][1], o0.z, o0.w);
        unpack2(acc[i][2], o1.x, o1.y);
        unpack2(acc[i][3], o1.z, o1.w);
        float* dst = &g_a[(size_t)pix * F + f0];
        *(float4*)dst = o0;
        *(float4*)(dst + 4) = o1;
    }
}

// ------------------------- exact top-k (sorted lanes + redux) --------------
// Monotonic uint transform + lane-local descending sort (Batcher, static
// indices) + shift-register selection using __reduce_max_sync. Same exact
// T semantics (k-th largest with multiplicity, keep >= T).
#define CE(i, j) { unsigned x_ = u[i], y_ = u[j]; \
                   u[i] = x_ > y_ ? x_ : y_; u[j] = x_ > y_ ? y_ : x_; }

__global__ void __launch_bounds__(256) topk_kernel() {
    int warp = blockIdx.x * 8 + (threadIdx.x >> 5);
    int lane = threadIdx.x & 31;
    if (warp >= NPIX) return;
    const float* ap = g_a + (size_t)warp * F;

    float v[16];
#pragma unroll
    for (int j = 0; j < 16; j++) v[j] = ap[j * 32 + lane];

    unsigned u[16];
#pragma unroll
    for (int j = 0; j < 16; j++) u[j] = fkey(v[j]);

    // Batcher odd-even mergesort, 16 elements, descending (63 CEs)
    CE(0,1) CE(2,3) CE(4,5) CE(6,7) CE(8,9) CE(10,11) CE(12,13) CE(14,15)
    CE(0,2) CE(1,3) CE(4,6) CE(5,7) CE(8,10) CE(9,11) CE(12,14) CE(13,15)
    CE(1,2) CE(5,6) CE(9,10) CE(13,14)
    CE(0,4) CE(1,5) CE(2,6) CE(3,7) CE(8,12) CE(9,13) CE(10,14) CE(11,15)
    CE(2,4) CE(3,5) CE(10,12) CE(11,13)
    CE(1,2) CE(3,4) CE(5,6) CE(9,10) CE(11,12) CE(13,14)
    CE(0,8) CE(1,9) CE(2,10) CE(3,11) CE(4,12) CE(5,13) CE(6,14) CE(7,15)
    CE(4,8) CE(5,9) CE(6,10) CE(7,11)
    CE(2,4) CE(3,5) CE(6,8) CE(7,9) CE(10,12) CE(11,13)
    CE(1,2) CE(3,4) CE(5,6) CE(7,8) CE(9,10) CE(11,12) CE(13,14)

    // selection: find Tu = key of 16th largest (with multiplicity)
    int removed = 0;
    unsigned Tu = 0;
#pragma unroll 1
    for (int it = 0; it < 16; it++) {
        unsigned h = u[0];
        unsigned mx = __reduce_max_sync(0xffffffffu, h);
        int c = __popc(__ballot_sync(0xffffffffu, h == mx));
        Tu = mx;
        if (removed + c >= 16) break;
        removed += c;
        if (h == mx) {
#pragma unroll
            for (int j = 0; j < 15; j++) u[j] = u[j + 1];
            u[15] = 0u;
        }
    }

    // compaction: keep all values with key >= Tu (== v >= T in float order)
    int base = 0;
#pragma unroll
    for (int j = 0; j < 16; j++) {
        bool keep = fkey(v[j]) >= Tu;
        unsigned bal = __ballot_sync(0xffffffffu, keep);
        if (keep) {
            int pos = base + __popc(bal & ((1u << lane) - 1u));
            if (pos < 32) {
                g_spidx[warp * 32 + pos] = j * 32 + lane;
                g_spval[warp * 32 + pos] = v[j];
            }
        }
        base += __popc(bal);
    }
    if (lane == 0) g_spcnt[warp] = base < 32 ? base : 32;
}
#undef CE

// ------------------------- sparse adjoint recon + aux (float4/channel) -----
template<int CIN, int STRIDE, int HIN, bool L1>
__global__ void __launch_bounds__(256) recon_aux_kernel(const float* __restrict__ refp) {
    const int TPP = CIN / 4;            // threads per pixel
    const int PPB = 256 / TPP;          // pixels per block
    int tid = threadIdx.x;
    int cg = tid % TPP;
    int c0 = cg * 4;
    int pi = tid / TPP;
    int g = blockIdx.x * PPB + pi;
    int n = g / (HIN * HIN);
    int r = g - n * (HIN * HIN);
    int y = r / HIN, xx = r - y * HIN;
    const float* wrb = L1 ? g_wr1 : g_wr0;

    float4 recon = {0.f, 0.f, 0.f, 0.f};
#pragma unroll
    for (int ky = 0; ky < 3; ky++) {
        int t = y + 1 - ky;
        int oy;
        if (STRIDE == 2) { if (t & 1) continue; oy = t >> 1; } else oy = t;
        if ((unsigned)oy >= 28u) continue;
#pragma unroll
        for (int kx = 0; kx < 3; kx++) {
            int s = xx + 1 - kx;
            int ox;
            if (STRIDE == 2) { if (s & 1) continue; ox = s >> 1; } else ox = s;
            if ((unsigned)ox >= 28u) continue;
            int q = (n * 28 + oy) * 28 + ox;
            int cnt = g_spcnt[q];
            const float* wb = wrb + (size_t)(ky * 3 + kx) * F * CIN + c0;
            const int4*   ip = (const int4*)&g_spidx[q * 32];
            const float4* vp = (const float4*)&g_spval[q * 32];
            int nb = cnt >> 2;
            for (int b = 0; b < nb; b++) {
                int4   f4 = ip[b];
                float4 v4 = vp[b];
                float4 w0 = *(const float4*)&wb[f4.x * CIN];
                float4 w1 = *(const float4*)&wb[f4.y * CIN];
                float4 w2 = *(const float4*)&wb[f4.z * CIN];
                float4 w3 = *(const float4*)&wb[f4.w * CIN];
                recon.x += v4.x * w0.x; recon.y += v4.x * w0.y;
                recon.z += v4.x * w0.z; recon.w += v4.x * w0.w;
                recon.x += v4.y * w1.x; recon.y += v4.y * w1.y;
                recon.z += v4.y * w1.z; recon.w += v4.y * w1.w;
                recon.x += v4.z * w2.x; recon.y += v4.z * w2.y;
                recon.z += v4.z * w2.z; recon.w += v4.z * w2.w;
                recon.x += v4.w * w3.x; recon.y += v4.w * w3.y;
                recon.z += v4.w * w3.z; recon.w += v4.w * w3.w;
            }
            for (int e = nb * 4; e < cnt; e++) {
                float vv = g_spval[q * 32 + e];
                const float4 ww = *(const float4*)&wb[g_spidx[q * 32 + e] * CIN];
                recon.x += vv * ww.x; recon.y += vv * ww.y;
                recon.z += vv * ww.z; recon.w += vv * ww.w;
            }
        }
    }
    const float* refbase = L1 ? (const float*)g_out0 : refp;
    size_t ridx = ((size_t)(n * CIN + c0) * HIN + y) * HIN + xx;
    const size_t cs = (size_t)HIN * HIN;
    float d0 = recon.x - refbase[ridx];
    float d1 = recon.y - refbase[ridx + cs];
    float d2 = recon.z - refbase[ridx + 2 * cs];
    float d3 = recon.w - refbase[ridx + 3 * cs];
    float dd = d0 * d0 + d1 * d1 + d2 * d2 + d3 * d3;

    __shared__ float red[256];
    red[tid] = dd;
    __syncthreads();
    for (int st = 128; st > 0; st >>= 1) {
        if (tid < st) red[tid] += red[tid + st];
        __syncthreads();
    }
    if (tid == 0) g_partial[blockIdx.x] = red[0];
}

__global__ void reduce_partials(int n, float scale, float* __restrict__ out) {
    __shared__ float red[256];
    float s = 0.f;
    for (int i = threadIdx.x; i < n; i += 256) s += g_partial[i];
    red[threadIdx.x] = s;
    __syncthreads();
    for (int st = 128; st > 0; st >>= 1) {
        if (threadIdx.x < st) red[threadIdx.x] += red[threadIdx.x + st];
        __syncthreads();
    }
    if (threadIdx.x == 0) *out = red[0] * scale;
}

// ------------------------- sparse 1x1 projection (unrolled x4) -------------
__global__ void __launch_bounds__(256) proj_kernel(int slot) {
    float* out = (slot == 0) ? g_out0 : g_p1;
    const float* wp = (slot == 0) ? g_wpT0 : g_wpT1;
    int tid = threadIdx.x;
    int co = tid & 127;
    int pi = tid >> 7;
    int q = blockIdx.x * 2 + pi;
    int cnt = g_spcnt[q];
    const int4*   ip = (const int4*)&g_spidx[q * 32];
    const float4* vp = (const float4*)&g_spval[q * 32];
    float acc = 0.f;
    int nb = cnt >> 2;
    for (int b = 0; b < nb; b++) {
        int4   f4 = ip[b];
        float4 v4 = vp[b];
        float w0 = wp[f4.x * COUT + co];
        float w1 = wp[f4.y * COUT + co];
        float w2 = wp[f4.z * COUT + co];
        float w3 = wp[f4.w * COUT + co];
        acc += v4.x * w0;
        acc += v4.y * w1;
        acc += v4.z * w2;
        acc += v4.w * w3;
    }
    for (int e = nb * 4; e < cnt; e++)
        acc += g_spval[q * 32 + e] * wp[g_spidx[q * 32 + e] * COUT + co];
    int n = q / 784, r = q - n * 784;
    out[(size_t)(n * COUT + co) * 784 + r] = acc;
}

// ------------------------- shortcut 1x1 stride-2 ---------------------------
__global__ void __launch_bounds__(256) shortcut_kernel(const float* __restrict__ x) {
    int tid = threadIdx.x;
    int co = tid & 127;
    int pi = tid >> 7;
    int q = blockIdx.x * 2 + pi;
    int n = q / 784, r = q - n * 784;
    int oy = r / 28, ox = r - oy * 28;
    const float* xp = x + (size_t)n * 64 * 3136 + (2 * oy) * 56 + 2 * ox;
    float acc = 0.f;
#pragma unroll
    for (int c = 0; c < 64; c++) acc = fmaf(xp[c * 3136], g_wscT[c * 128 + co], acc);
    g_psc[(size_t)(n * COUT + co) * 784 + r] = acc;
}

// ------------------------- batchnorm stats (two-stage, double) -------------
__global__ void __launch_bounds__(256) bn_stage1(int slot) {
    const float* src = (slot == 0) ? g_out0 : (slot == 1 ? g_p1 : g_psc);
    int co = blockIdx.x;
    int chunk = blockIdx.y;
    int tid = threadIdx.x;
    double s = 0.0, s2 = 0.0;
    for (int n = chunk * 4; n < chunk * 4 + 4; n++) {
        const float* row = src + (size_t)(n * COUT + co) * 784;
        for (int r = tid; r < 784; r += 256) {
            double v = (double)row[r];
            s += v; s2 += v * v;
        }
    }
    __shared__ double rs[256], rq[256];
    rs[tid] = s; rq[tid] = s2;
    __syncthreads();
    for (int st = 128; st > 0; st >>= 1) {
        if (tid < st) { rs[tid] += rs[tid + st]; rq[tid] += rq[tid + st]; }
        __syncthreads();
    }
    if (tid == 0) g_bns[co * 16 + chunk] = make_double2(rs[0], rq[0]);
}
__global__ void bn_stage2(int slot) {
    int co = threadIdx.x;
    double s = 0.0, s2 = 0.0;
    for (int k = 0; k < 16; k++) {
        double2 p = g_bns[co * 16 + k];
        s += p.x; s2 += p.y;
    }
    double mean = s * (1.0 / 50176.0);
    double var = s2 * (1.0 / 50176.0) - mean * mean;
    g_mean[slot][co] = (float)mean;
    g_rstd[slot][co] = rsqrtf((float)var + BN_EPS);
}

__global__ void __launch_bounds__(256) norm0_kernel(const float* __restrict__ gg,
                                                    const float* __restrict__ bb) {
    size_t i = (size_t)blockIdx.x * 256 + threadIdx.x;
    if (i >= OUTN) return;
    int co = (int)((i / 784) & 127);
    g_out0[i] = ((g_out0[i] - g_mean[0][co]) * g_rstd[0][co]) * gg[co] + bb[co];
}

__global__ void __launch_bounds__(256) final_kernel(float* __restrict__ dout,
        const float* __restrict__ g1, const float* __restrict__ b1,
        const float* __restrict__ gsc, const float* __restrict__ bsc) {
    size_t i = (size_t)blockIdx.x * 256 + threadIdx.x;
    if (i >= OUTN) return;
    int co = (int)((i / 784) & 127);
    float v1 = ((g_p1[i]  - g_mean[1][co]) * g_rstd[1][co]) * g1[co]  + b1[co];
    float v2 = ((g_psc[i] - g_mean[2][co]) * g_rstd[2][co]) * gsc[co] + bsc[co];
    float v = v1 + v2;
    dout[i] = v > 0.f ? v : 0.f;
}

// ---------------------------------------------------------------------------
extern "C" void kernel_launch(void* const* d_in, const int* in_sizes, int n_in,
                              void* d_out, int out_size) {
    const float* x       = (const float*)d_in[0];
    const float* w_enc0  = (const float*)d_in[1];
    const float* w_proj0 = (const float*)d_in[2];
    const float* g0      = (const float*)d_in[3];
    const float* b0      = (const float*)d_in[4];
    const float* w_enc1  = (const float*)d_in[5];
    const float* w_proj1 = (const float*)d_in[6];
    const float* g1      = (const float*)d_in[7];
    const float* b1      = (const float*)d_in[8];
    const float* w_sc    = (const float*)d_in[9];
    const float* g_sc    = (const float*)d_in[10];
    const float* b_sc    = (const float*)d_in[11];
    float* out = (float*)d_out;

    const int elem_blocks = (int)((OUTN + 255) / 256);
    dim3 bnGrid(128, 16);

    // ---------------- layer 0 ----------------
    prep_enc<<<(9 * 512 * 64 + 255) / 256, 256>>>(w_enc0, 64, 0);     // #1
    make_wpT<<<(512 * 128 + 255) / 256, 256>>>(w_proj0, 0);           // #2
    conv_enc<64, 2, 56, false><<<dim3(NPIX / 128, 4), 128>>>(x);      // #3
    topk_kernel<<<NPIX / 8, 256>>>();                                 // #4 <- profiled
    recon_aux_kernel<64, 2, 56, false><<<NIMG * 3136 / 16, 256>>>(x);
    reduce_partials<<<1, 256>>>(NIMG * 3136 / 16, 1.f / 12845056.f, out + out_size - 2);
    proj_kernel<<<NPIX / 2, 256>>>(0);
    bn_stage1<<<bnGrid, 256>>>(0);
    bn_stage2<<<1, 128>>>(0);
    norm0_kernel<<<elem_blocks, 256>>>(g0, b0);

    // ---------------- layer 1 ----------------
    prep_enc<<<(9 * 512 * 128 + 255) / 256, 256>>>(w_enc1, 128, 1);
    conv_enc<128, 1, 28, true><<<dim3(NPIX / 128, 4), 128>>>(x);
    topk_kernel<<<NPIX / 8, 256>>>();
    recon_aux_kernel<128, 1, 28, true><<<NIMG * 784 / 8, 256>>>(nullptr);
    reduce_partials<<<1, 256>>>(NIMG * 784 / 8, 1.f / 6422528.f, out + out_size - 1);
    make_wpT<<<(512 * 128 + 255) / 256, 256>>>(w_proj1, 1);
    proj_kernel<<<NPIX / 2, 256>>>(1);
    bn_stage1<<<bnGrid, 256>>>(1);
    bn_stage2<<<1, 128>>>(1);

    // ---------------- shortcut + fuse ----------------
    make_wscT<<<(64 * 128 + 255) / 256, 256>>>(w_sc);
    shortcut_kernel<<<NPIX / 2, 256>>>(x);
    bn_stage1<<<bnGrid, 256>>>(2);
    bn_stage2<<<1, 128>>>(2);
    final_kernel<<<elem_blocks, 256>>>(out, g1, b1, g_sc, b_sc);
}